// round 9
// baseline (speedup 1.0000x reference)
#include <cuda_runtime.h>
#include <cuda_fp16.h>
#include <cstdint>

#define BATCH 2
#define SLEN  8192
#define HID   1024
#define NSEG  4
#define NPTS  512
#define NHEAD 16
#define DHEAD 64
#define WSEG  2048
#define NCOL  768
#define STR   72   // attn smem stride (fp16)

#define GSIZE (BATCH*NSEG*NHEAD*NPTS*DHEAD)
__device__ __align__(16) __half g_Xh[BATCH*SLEN*HID];
__device__ __align__(16) __half g_Xl[BATCH*SLEN*HID];
__device__ __align__(16) __half g_Wp[4*NCOL*HID];             // [r][n][k] hi only
__device__ __align__(16) __half g_Qh[GSIZE], g_Ql[GSIZE];     // [b][seg][h][p][d], pre-scaled
__device__ __align__(16) __half g_Kh[GSIZE];                  // [b][seg][h][p][d]
__device__ __align__(16) __half g_Vth[GSIZE], g_Vtl[GSIZE];   // [b][seg][h][d][p]

// ---------------------------------------------------------------------------
__device__ __forceinline__ void ldm_x4(uint32_t* r, uint32_t addr) {
    asm volatile("ldmatrix.sync.aligned.m8n8.x4.shared.b16 {%0,%1,%2,%3}, [%4];\n"
                 : "=r"(r[0]), "=r"(r[1]), "=r"(r[2]), "=r"(r[3]) : "r"(addr));
}
__device__ __forceinline__ void mma16816(float* c, const uint32_t* a,
                                         uint32_t b0, uint32_t b1) {
    asm volatile("mma.sync.aligned.m16n8k16.row.col.f32.f16.f16.f32 "
                 "{%0,%1,%2,%3}, {%4,%5,%6,%7}, {%8,%9}, {%0,%1,%2,%3};\n"
                 : "+f"(c[0]), "+f"(c[1]), "+f"(c[2]), "+f"(c[3])
                 : "r"(a[0]), "r"(a[1]), "r"(a[2]), "r"(a[3]), "r"(b0), "r"(b1));
}
__device__ __forceinline__ void cp16(uint32_t dst, const void* src) {
    asm volatile("cp.async.cg.shared.global [%0], [%1], 16;\n" :: "r"(dst), "l"(src));
}
__device__ __forceinline__ void cp_commit() { asm volatile("cp.async.commit_group;\n"); }
__device__ __forceinline__ void cp_waitall() { asm volatile("cp.async.wait_group 0;\n"); }

__device__ __forceinline__ void pack_hl(float x, float y, uint32_t& hi, uint32_t& lo) {
    __half hx = __float2half_rn(x), hy = __float2half_rn(y);
    __half lx = __float2half_rn(x - __half2float(hx));
    __half ly = __float2half_rn(y - __half2float(hy));
    __half2 h2; h2.x = hx; h2.y = hy;
    __half2 l2; l2.x = lx; l2.y = ly;
    hi = *(uint32_t*)&h2; lo = *(uint32_t*)&l2;
}
// SW128 swizzle on 128-byte rows
__device__ __forceinline__ uint32_t sw128(uint32_t off) {
    return off ^ ((off >> 3) & 0x70);
}

// ---------------------------------------------------------------------------
__global__ __launch_bounds__(256) void splitx(const float4* __restrict__ X4)
{
    long i = (long)blockIdx.x * 256 + threadIdx.x;
    float4 v = X4[i];
    __half2 h01, h23, l01, l23;
    h01.x = __float2half_rn(v.x); h01.y = __float2half_rn(v.y);
    h23.x = __float2half_rn(v.z); h23.y = __float2half_rn(v.w);
    l01.x = __float2half_rn(v.x - __half2float(h01.x));
    l01.y = __float2half_rn(v.y - __half2float(h01.y));
    l23.x = __float2half_rn(v.z - __half2float(h23.x));
    l23.y = __float2half_rn(v.w - __half2float(h23.y));
    __half2* H2 = (__half2*)g_Xh;
    __half2* L2 = (__half2*)g_Xl;
    H2[2*i] = h01; H2[2*i+1] = h23;
    L2[2*i] = l01; L2[2*i+1] = l23;
}

// ---------------------------------------------------------------------------
__global__ __launch_bounds__(256) void wpack(const float* __restrict__ Wq,
                                             const float* __restrict__ Wkv)
{
    __shared__ float s[32][33];
    int tx = threadIdx.x & 31, ty = threadIdx.x >> 5;
    int r = blockIdx.z;
    int n = blockIdx.y * 32 + tx;
    int g = n >> 8, cc = n & 255;
    int h = r + 4 * (cc >> 6), d = cc & 63;
    const float* src; long stride;
    if (g == 0)      { src = Wq  + h*64 + d;        stride = 1024; }
    else if (g == 1) { src = Wkv + h*64 + d;        stride = 2048; }
    else             { src = Wkv + 1024 + h*64 + d; stride = 2048; }
    #pragma unroll
    for (int i = 0; i < 4; ++i) {
        int k = blockIdx.x * 32 + ty + i * 8;
        s[ty + i*8][tx] = src[(long)k * stride];
    }
    __syncthreads();
    long rbase = (long)r * NCOL * HID;
    #pragma unroll
    for (int i = 0; i < 4; ++i) {
        int nl = ty + i * 8;
        float v = s[tx][nl];
        long idx = (long)(blockIdx.y * 32 + nl) * HID + blockIdx.x * 32 + tx;
        g_Wp[rbase + idx] = __float2half_rn(v);
    }
}

// ---------------------------------------------------------------------------
// proj fp16x2, cp.async double-buffered, k-blocks of 64 (4 k16 steps/stage).
// Stage layout (SW128, 128B rows): Xh[128 rows] | Xl[128] | W[128], 16KB each.
// ---------------------------------------------------------------------------
#define PA   16384
#define PSTG (3*PA)   // 49152 per stage

__global__ __launch_bounds__(256) void proj_cp(const float* __restrict__ bq,
                                               const float* __restrict__ bkv)
{
    extern __shared__ __half psm[];
    const uint32_t base = (uint32_t)__cvta_generic_to_shared(psm);

    const int tid  = threadIdx.x;
    const int lane = tid & 31, warp = tid >> 5;
    const int wm = warp >> 2, wn = warp & 3;
    const int b  = blockIdx.z >> 2;
    const int r  = blockIdx.z & 3;
    const int m0 = blockIdx.y * 128;
    const int n0 = blockIdx.x * 128;

    // loader mapping: 4 chunks per array per thread; chunk c -> row c>>3, 16B col c&7
    const __half* aHp[4]; const __half* aLp[4]; const __half* bWp[4];
    uint32_t sAdr[4];
    #pragma unroll
    for (int q = 0; q < 4; ++q) {
        int c = tid + q * 256;
        int row = c >> 3, col = c & 7;
        aHp[q] = g_Xh + ((long)b * SLEN + (4*(m0 + row) + r)) * HID + col*8;
        aLp[q] = g_Xl + ((long)b * SLEN + (4*(m0 + row) + r)) * HID + col*8;
        bWp[q] = g_Wp + ((long)r * NCOL + n0 + row) * HID + col*8;
        sAdr[q] = sw128((uint32_t)(row*128 + col*16));
    }

    // preload stage 0
    #pragma unroll
    for (int q = 0; q < 4; ++q) {
        cp16(base + sAdr[q],          aHp[q]);
        cp16(base + PA + sAdr[q],     aLp[q]);
        cp16(base + 2*PA + sAdr[q],   bWp[q]);
    }
    cp_commit();

    const int lrow16 = (lane & 7) + ((lane >> 3) & 1) * 8;
    const int kbyt   = (lane >> 4) * 16;

    float acc[4][4][4];
    #pragma unroll
    for (int i = 0; i < 4; ++i)
        #pragma unroll
        for (int j = 0; j < 4; ++j)
            #pragma unroll
            for (int q = 0; q < 4; ++q) acc[i][j][q] = 0.f;

    for (int kb = 0; kb < 16; ++kb) {
        if (kb < 15) {
            const uint32_t nb = base + (uint32_t)(((kb + 1) & 1)) * PSTG;
            const int ko = (kb + 1) * 64;
            #pragma unroll
            for (int q = 0; q < 4; ++q) {
                cp16(nb + sAdr[q],        aHp[q] + ko);
                cp16(nb + PA + sAdr[q],   aLp[q] + ko);
                cp16(nb + 2*PA + sAdr[q], bWp[q] + ko);
            }
            cp_commit();
            asm volatile("cp.async.wait_group 1;" ::: "memory");
        } else {
            cp_waitall();
        }
        __syncthreads();

        const uint32_t sAh = base + (uint32_t)(kb & 1) * PSTG;
        const uint32_t sAl = sAh + PA;
        const uint32_t sBw = sAh + 2*PA;

        #pragma unroll
        for (int kk = 0; kk < 4; ++kk) {
            const uint32_t cb = (uint32_t)(kk*32 + kbyt);
            uint32_t fbh[2][4];
            ldm_x4(fbh[0], sBw + sw128((uint32_t)((wn*32 + lrow16)*128) + cb));
            ldm_x4(fbh[1], sBw + sw128((uint32_t)((wn*32 + 16 + lrow16)*128) + cb));
            #pragma unroll
            for (int mi = 0; mi < 4; ++mi) {
                uint32_t fah[4], fal[4];
                uint32_t ra = (uint32_t)((wm*64 + mi*16 + lrow16)*128) + cb;
                ldm_x4(fah, sAh + sw128(ra));
                ldm_x4(fal, sAl + sw128(ra));
                #pragma unroll
                for (int nj = 0; nj < 4; ++nj) {
                    int t = nj >> 1, s = nj & 1;
                    float* c = acc[mi][nj];
                    mma16816(c, fah, fbh[t][s], fbh[t][s+2]);
                    mma16816(c, fal, fbh[t][s], fbh[t][s+2]);
                }
            }
        }
        __syncthreads();
    }

    // epilogue
    const int group = lane >> 2, tig = lane & 3;
    #pragma unroll
    for (int mi = 0; mi < 4; ++mi) {
        #pragma unroll
        for (int nj = 0; nj < 4; ++nj) {
            int nl = wn*32 + nj*8 + tig*2;
            int c  = n0 + nl;
            int g  = c >> 8, cc = c & 255;
            int hh = r + 4 * (cc >> 6), d = cc & 63;
            const float* barr = (g == 0) ? bq : (g == 1) ? bkv : bkv + 1024;
            float b0v = barr[hh*64 + d], b1v = barr[hh*64 + d + 1];
            #pragma unroll
            for (int half = 0; half < 2; ++half) {
                int jrow = m0 + wm*64 + mi*16 + group + half*8;
                int seg = jrow >> 9, p = jrow & 511;
                float vx = acc[mi][nj][half*2 + 0] + b0v;
                float vy = acc[mi][nj][half*2 + 1] + b1v;
                long bsh = (long)((b*NSEG + seg)*NHEAD + hh);
                if (g == 0) {
                    vx *= 0.125f; vy *= 0.125f;
                    uint32_t hi, lo;
                    pack_hl(vx, vy, hi, lo);
                    long idx = (bsh*NPTS + p)*DHEAD + d;
                    *(uint32_t*)&g_Qh[idx] = hi;
                    *(uint32_t*)&g_Ql[idx] = lo;
                } else if (g == 1) {
                    __half2 hv; hv.x = __float2half_rn(vx); hv.y = __float2half_rn(vy);
                    long idx = (bsh*NPTS + p)*DHEAD + d;
                    *(__half2*)&g_Kh[idx] = hv;
                } else {
                    __half hx = __float2half_rn(vx), hy = __float2half_rn(vy);
                    __half lx = __float2half_rn(vx - __half2float(hx));
                    __half ly = __float2half_rn(vy - __half2float(hy));
                    long idx = (bsh*DHEAD + d)*NPTS + p;
                    g_Vth[idx] = hx; g_Vth[idx + NPTS] = hy;
                    g_Vtl[idx] = lx; g_Vtl[idx + NPTS] = ly;
                }
            }
        }
    }
}

// ---------------------------------------------------------------------------
// Flash attention fp16 (R6) + zero-fill of sibling-head channels (no memset).
// ---------------------------------------------------------------------------
#define BUFE (192*STR)
#define QOFF (2*BUFE)

__global__ __launch_bounds__(256) void attn_mma(float* __restrict__ out)
{
    extern __shared__ __half sbm[];
    const int tid = threadIdx.x;
    const int lane = tid & 31, warp = tid >> 5;
    const int qt = blockIdx.x, h = blockIdx.y, bs = blockIdx.z;
    const int b = bs >> 2, seg = bs & 3;
    const long base = (long)(bs*NHEAD + h) * (NPTS*DHEAD);

    const uint32_t sm0 = (uint32_t)__cvta_generic_to_shared(sbm);

    const int lm = tid / 64, lj = tid & 63;
    const bool ldr = tid < 192;
    const __half* csrc = nullptr;
    long cstep = 0;
    uint32_t cdst = 0;
    if (ldr) {
        if      (lm == 0) { csrc = g_Kh  + base + lj*DHEAD;      cstep = 64*DHEAD; }
        else if (lm == 1) { csrc = g_Vth + base + (long)lj*NPTS; cstep = 64; }
        else              { csrc = g_Vtl + base + (long)lj*NPTS; cstep = 64; }
        cdst = sm0 + (uint32_t)((lm*64 + lj)*STR)*2;
    }

    {
        int qhf = tid >> 7, qrow = tid & 127;
        const __half* qs = (qhf ? g_Ql : g_Qh) + base + (long)(qt*128 + qrow)*DHEAD;
        uint32_t qd = sm0 + (uint32_t)(QOFF + (qhf*128 + qrow)*STR)*2;
        #pragma unroll
        for (int i = 0; i < 8; ++i) cp16(qd + i*16, qs + i*8);
        if (ldr) {
            #pragma unroll
            for (int i = 0; i < 8; ++i) cp16(cdst + i*16, csrc + i*8);
        }
    }
    cp_commit();
    cp_waitall();
    __syncthreads();

    const int lrow16 = (lane & 7) + ((lane >> 3) & 1) * 8;
    const int kbyt   = (lane >> 4) * 16;

    uint32_t qh[4][4], ql[4][4];
    {
        uint32_t qa = sm0 + (uint32_t)(QOFF + (warp*16 + lrow16)*STR)*2 + kbyt;
        #pragma unroll
        for (int kk = 0; kk < 4; ++kk) {
            ldm_x4(qh[kk], qa + kk*32);
            ldm_x4(ql[kk], qa + 128*STR*2 + kk*32);
        }
    }
    if (ldr) {
        const __half* s = csrc + cstep;
        uint32_t d = cdst + (uint32_t)BUFE*2;
        #pragma unroll
        for (int i = 0; i < 8; ++i) cp16(d + i*16, s + i*8);
    }
    cp_commit();

    float m0 = -1e30f, m1 = -1e30f, l0 = 0.f, l1 = 0.f;
    float o[8][4];
    #pragma unroll
    for (int j = 0; j < 8; ++j)
        #pragma unroll
        for (int q = 0; q < 4; ++q) o[j][q] = 0.f;

    for (int ck = 0; ck < 8; ++ck) {
        const uint32_t sK  = sm0 + (uint32_t)(ck & 1)*BUFE*2;
        const uint32_t sV  = sK + 64*STR*2;
        const uint32_t sVl = sK + 128*STR*2;

        float sc[8][4];
        #pragma unroll
        for (int j = 0; j < 8; ++j)
            #pragma unroll
            for (int q = 0; q < 4; ++q) sc[j][q] = 0.f;

        #pragma unroll
        for (int kk = 0; kk < 4; ++kk) {
            uint32_t kbh[4][4];
            #pragma unroll
            for (int kg = 0; kg < 4; ++kg) {
                uint32_t a = (uint32_t)((kg*16 + lrow16)*STR*2 + kk*32 + kbyt);
                ldm_x4(kbh[kg], sK + a);
            }
            #pragma unroll
            for (int kg = 0; kg < 4; ++kg)
                #pragma unroll
                for (int s = 0; s < 2; ++s) {
                    float* c = sc[kg*2 + s];
                    mma16816(c, qh[kk], kbh[kg][s], kbh[kg][s+2]);
                    mma16816(c, ql[kk], kbh[kg][s], kbh[kg][s+2]);
                }
        }

        float mc0 = -1e30f, mc1 = -1e30f;
        #pragma unroll
        for (int j = 0; j < 8; ++j) {
            mc0 = fmaxf(mc0, fmaxf(sc[j][0], sc[j][1]));
            mc1 = fmaxf(mc1, fmaxf(sc[j][2], sc[j][3]));
        }
        mc0 = fmaxf(mc0, __shfl_xor_sync(0xffffffffu, mc0, 1));
        mc0 = fmaxf(mc0, __shfl_xor_sync(0xffffffffu, mc0, 2));
        mc1 = fmaxf(mc1, __shfl_xor_sync(0xffffffffu, mc1, 1));
        mc1 = fmaxf(mc1, __shfl_xor_sync(0xffffffffu, mc1, 2));
        float mn0 = fmaxf(m0, mc0), mn1 = fmaxf(m1, mc1);
        float a0 = __expf(m0 - mn0), a1 = __expf(m1 - mn1);
        float s0 = 0.f, s1 = 0.f;
        #pragma unroll
        for (int j = 0; j < 8; ++j) {
            sc[j][0] = __expf(sc[j][0] - mn0);
            sc[j][1] = __expf(sc[j][1] - mn0);
            sc[j][2] = __expf(sc[j][2] - mn1);
            sc[j][3] = __expf(sc[j][3] - mn1);
            s0 += sc[j][0] + sc[j][1];
            s1 += sc[j][2] + sc[j][3];
        }
        s0 += __shfl_xor_sync(0xffffffffu, s0, 1);
        s0 += __shfl_xor_sync(0xffffffffu, s0, 2);
        s1 += __shfl_xor_sync(0xffffffffu, s1, 1);
        s1 += __shfl_xor_sync(0xffffffffu, s1, 2);
        l0 = l0*a0 + s0; l1 = l1*a1 + s1;
        m0 = mn0; m1 = mn1;
        #pragma unroll
        for (int j = 0; j < 8; ++j) {
            o[j][0] *= a0; o[j][1] *= a0;
            o[j][2] *= a1; o[j][3] *= a1;
        }

        uint32_t ph[4][4], pl[4][4];
        #pragma unroll
        for (int t = 0; t < 4; ++t) {
            pack_hl(sc[2*t  ][0], sc[2*t  ][1], ph[t][0], pl[t][0]);
            pack_hl(sc[2*t  ][2], sc[2*t  ][3], ph[t][1], pl[t][1]);
            pack_hl(sc[2*t+1][0], sc[2*t+1][1], ph[t][2], pl[t][2]);
            pack_hl(sc[2*t+1][2], sc[2*t+1][3], ph[t][3], pl[t][3]);
        }

        #pragma unroll
        for (int t = 0; t < 4; ++t) {
            uint32_t vbh[4][4], vbl[4][4];
            #pragma unroll
            for (int nt = 0; nt < 4; ++nt) {
                uint32_t a = (uint32_t)((nt*16 + lrow16)*STR*2 + t*32 + kbyt);
                ldm_x4(vbh[nt], sV + a);
                ldm_x4(vbl[nt], sVl + a);
            }
            #pragma unroll
            for (int nt = 0; nt < 4; ++nt)
                #pragma unroll
                for (int s = 0; s < 2; ++s) {
                    float* c = o[nt*2 + s];
                    mma16816(c, ph[t], vbh[nt][s], vbh[nt][s+2]);
                    mma16816(c, pl[t], vbh[nt][s], vbh[nt][s+2]);
                    mma16816(c, ph[t], vbl[nt][s], vbl[nt][s+2]);
                }
        }

        cp_waitall();
        __syncthreads();
        if (ck + 2 < 8 && ldr) {
            const __half* s = csrc + (long)(ck + 2)*cstep;
            uint32_t d = cdst + (uint32_t)(ck & 1)*BUFE*2;
            #pragma unroll
            for (int i = 0; i < 8; ++i) cp16(d + i*16, s + i*8);
        }
        if (ck + 2 < 8) cp_commit();
    }

    // epilogue: ctx for this head + zeros for the 3 sibling heads (replaces memset)
    float inv0 = 1.f / l0, inv1 = 1.f / l1;
    int r0 = lane >> 2, dc = (lane & 3) * 2;
    int p0 = qt*128 + warp*16 + r0;
    int s0p = seg*WSEG + 4*p0 + (h & 3);
    int s1p = s0p + 32;
    float* ob0 = out + ((long)b*SLEN + s0p)*HID + h*DHEAD + dc;
    float* ob1 = out + ((long)b*SLEN + s1p)*HID + h*DHEAD + dc;
    const float2 z2 = make_float2(0.f, 0.f);
    #pragma unroll
    for (int j = 0; j < 8; ++j) {
        float2 v0 = make_float2(o[j][0]*inv0, o[j][1]*inv0);
        float2 v1 = make_float2(o[j][2]*inv1, o[j][3]*inv1);
        *(float2*)(ob0 + j*8) = v0;
        *(float2*)(ob1 + j*8) = v1;
        #pragma unroll
        for (int m = 1; m < 4; ++m) {
            long doff = (long)((h ^ m) - h) * DHEAD;
            *(float2*)(ob0 + doff + j*8) = z2;
            *(float2*)(ob1 + doff + j*8) = z2;
        }
    }
}

// ---------------------------------------------------------------------------
extern "C" void kernel_launch(void* const* d_in, const int* in_sizes, int n_in,
                              void* d_out, int out_size)
{
    const float* X   = (const float*)d_in[0];
    const float* Wq  = (const float*)d_in[1];
    const float* bq  = (const float*)d_in[2];
    const float* Wkv = (const float*)d_in[3];
    const float* bkv = (const float*)d_in[4];
    float* out = (float*)d_out;

    splitx<<<BATCH*SLEN*HID/4/256, 256>>>((const float4*)X);

    dim3 gw(HID/32, NCOL/32, 4);
    wpack<<<gw, 256>>>(Wq, Wkv);

    const int psm = 2 * PSTG;   // 98304 B
    cudaFuncSetAttribute(proj_cp, cudaFuncAttributeMaxDynamicSharedMemorySize, psm);
    dim3 g1(NCOL/128, 16, BATCH * 4);
    proj_cp<<<g1, 256, psm>>>(bq, bkv);

    const int smem = (2*BUFE + 256*STR) * (int)sizeof(__half);   // 92160 B
    cudaFuncSetAttribute(attn_mma, cudaFuncAttributeMaxDynamicSharedMemorySize, smem);
    dim3 g2(4, NHEAD, BATCH * NSEG);
    attn_mma<<<g2, 256, smem>>>(out);
}

// round 11
// speedup vs baseline: 1.2891x; 1.2891x over previous
#include <cuda_runtime.h>
#include <cuda_fp16.h>
#include <cstdint>

#define BATCH 2
#define SLEN  8192
#define HID   1024
#define NSEG  4
#define NPTS  512
#define NHEAD 16
#define DHEAD 64
#define WSEG  2048
#define NCOL  768
#define STRB  24   // proj smem stride (fp16)
#define STR   72   // attn smem stride (fp16)

#define GSIZE (BATCH*NSEG*NHEAD*NPTS*DHEAD)
__device__ __align__(16) __half g_Xh[BATCH*SLEN*HID];
__device__ __align__(16) __half g_Xl[BATCH*SLEN*HID];
__device__ __align__(16) __half g_Wp[4*NCOL*HID];             // [r][n][k] hi only
__device__ __align__(16) __half g_Qh[GSIZE], g_Ql[GSIZE];     // [b][seg][h][p][d], pre-scaled
__device__ __align__(16) __half g_Kh[GSIZE];                  // [b][seg][h][p][d]
__device__ __align__(16) __half g_Vth[GSIZE], g_Vtl[GSIZE];   // [b][seg][h][d][p]

// ---------------------------------------------------------------------------
__device__ __forceinline__ void ldm_x4(uint32_t* r, uint32_t addr) {
    asm volatile("ldmatrix.sync.aligned.m8n8.x4.shared.b16 {%0,%1,%2,%3}, [%4];\n"
                 : "=r"(r[0]), "=r"(r[1]), "=r"(r[2]), "=r"(r[3]) : "r"(addr));
}
__device__ __forceinline__ void mma16816(float* c, const uint32_t* a,
                                         uint32_t b0, uint32_t b1) {
    asm volatile("mma.sync.aligned.m16n8k16.row.col.f32.f16.f16.f32 "
                 "{%0,%1,%2,%3}, {%4,%5,%6,%7}, {%8,%9}, {%0,%1,%2,%3};\n"
                 : "+f"(c[0]), "+f"(c[1]), "+f"(c[2]), "+f"(c[3])
                 : "r"(a[0]), "r"(a[1]), "r"(a[2]), "r"(a[3]), "r"(b0), "r"(b1));
}
__device__ __forceinline__ void cp16(uint32_t dst, const void* src) {
    asm volatile("cp.async.cg.shared.global [%0], [%1], 16;\n" :: "r"(dst), "l"(src));
}
__device__ __forceinline__ void cp_commit() { asm volatile("cp.async.commit_group;\n"); }
__device__ __forceinline__ void cp_waitall() { asm volatile("cp.async.wait_group 0;\n"); }

__device__ __forceinline__ void pack_hl(float x, float y, uint32_t& hi, uint32_t& lo) {
    __half hx = __float2half_rn(x), hy = __float2half_rn(y);
    __half lx = __float2half_rn(x - __half2float(hx));
    __half ly = __float2half_rn(y - __half2float(hy));
    __half2 h2; h2.x = hx; h2.y = hy;
    __half2 l2; l2.x = lx; l2.y = ly;
    hi = *(uint32_t*)&h2; lo = *(uint32_t*)&l2;
}
__device__ __forceinline__ uint32_t pack_h(float x, float y) {
    __half2 h2; h2.x = __float2half_rn(x); h2.y = __float2half_rn(y);
    return *(uint32_t*)&h2;
}

// ---------------------------------------------------------------------------
__global__ __launch_bounds__(256) void splitx(const float4* __restrict__ X4)
{
    long i = (long)blockIdx.x * 256 + threadIdx.x;
    float4 v = X4[i];
    __half2 h01, h23, l01, l23;
    h01.x = __float2half_rn(v.x); h01.y = __float2half_rn(v.y);
    h23.x = __float2half_rn(v.z); h23.y = __float2half_rn(v.w);
    l01.x = __float2half_rn(v.x - __half2float(h01.x));
    l01.y = __float2half_rn(v.y - __half2float(h01.y));
    l23.x = __float2half_rn(v.z - __half2float(h23.x));
    l23.y = __float2half_rn(v.w - __half2float(h23.y));
    __half2* H2 = (__half2*)g_Xh;
    __half2* L2 = (__half2*)g_Xl;
    H2[2*i] = h01; H2[2*i+1] = h23;
    L2[2*i] = l01; L2[2*i+1] = l23;
}

// ---------------------------------------------------------------------------
__global__ __launch_bounds__(256) void wpack(const float* __restrict__ Wq,
                                             const float* __restrict__ Wkv)
{
    __shared__ float s[32][33];
    int tx = threadIdx.x & 31, ty = threadIdx.x >> 5;
    int r = blockIdx.z;
    int n = blockIdx.y * 32 + tx;
    int g = n >> 8, cc = n & 255;
    int h = r + 4 * (cc >> 6), d = cc & 63;
    const float* src; long stride;
    if (g == 0)      { src = Wq  + h*64 + d;        stride = 1024; }
    else if (g == 1) { src = Wkv + h*64 + d;        stride = 2048; }
    else             { src = Wkv + 1024 + h*64 + d; stride = 2048; }
    #pragma unroll
    for (int i = 0; i < 4; ++i) {
        int k = blockIdx.x * 32 + ty + i * 8;
        s[ty + i*8][tx] = src[(long)k * stride];
    }
    __syncthreads();
    long rbase = (long)r * NCOL * HID;
    #pragma unroll
    for (int i = 0; i < 4; ++i) {
        int nl = ty + i * 8;
        float v = s[tx][nl];
        long idx = (long)(blockIdx.y * 32 + nl) * HID + blockIdx.x * 32 + tx;
        g_Wp[rbase + idx] = __float2half_rn(v);
    }
}

// ---------------------------------------------------------------------------
// proj via fp16x2 mma (R6 structure) with 2 CTAs/SM forced via launch bounds.
// ---------------------------------------------------------------------------
__global__ __launch_bounds__(256, 2) void proj_mma(const float* __restrict__ bq,
                                                   const float* __restrict__ bkv)
{
    __shared__ __half sA[2][2][128*STRB];
    __shared__ __half sB[2][128*STRB];

    const int tid  = threadIdx.x;
    const int lane = tid & 31, warp = tid >> 5;
    const int wm = warp >> 2, wn = warp & 3;
    const int b  = blockIdx.z >> 2;
    const int r  = blockIdx.z & 3;
    const int m0 = blockIdx.y * 128;
    const int n0 = blockIdx.x * 128;

    const int lrow = tid & 127, lhalf = tid >> 7;
    const __half* aSrc =
        (lhalf ? g_Xl : g_Xh) + ((long)b * SLEN + (4*(m0 + lrow) + r)) * HID;
    const __half* bSrc = g_Wp + ((long)r * NCOL + n0 + lrow) * HID;

    const int lrow16 = (lane & 7) + ((lane >> 3) & 1) * 8;
    const int kbyt   = (lane >> 4) * 16;
    const uint32_t smA = (uint32_t)__cvta_generic_to_shared(&sA[0][0][0]);
    const uint32_t smB = (uint32_t)__cvta_generic_to_shared(&sB[0][0]);
    const uint32_t aoff = (uint32_t)((wm*64 + lrow16) * STRB * 2 + kbyt);
    const uint32_t boff = (uint32_t)((wn*32 + lrow16) * STRB * 2 + kbyt);

    float acc[4][4][4];
    #pragma unroll
    for (int i = 0; i < 4; ++i)
        #pragma unroll
        for (int j = 0; j < 4; ++j)
            #pragma unroll
            for (int q = 0; q < 4; ++q) acc[i][j][q] = 0.f;

    uint4 ra0 = *(const uint4*)(aSrc + 0);
    uint4 ra1 = *(const uint4*)(aSrc + 8);
    uint4 rb0, rb1;
    if (lhalf == 0) { rb0 = *(const uint4*)(bSrc + 0); rb1 = *(const uint4*)(bSrc + 8); }
    {
        uint4* dA = (uint4*)&sA[0][lhalf][lrow * STRB];
        dA[0] = ra0; dA[1] = ra1;
        if (lhalf == 0) {
            uint4* dB = (uint4*)&sB[0][lrow * STRB];
            dB[0] = rb0; dB[1] = rb1;
        }
    }
    __syncthreads();

    for (int kt = 0; kt < 64; ++kt) {
        const int cur = kt & 1;
        if (kt < 63) {
            int k0 = (kt + 1) * 16;
            ra0 = *(const uint4*)(aSrc + k0);
            ra1 = *(const uint4*)(aSrc + k0 + 8);
            if (lhalf == 0) {
                rb0 = *(const uint4*)(bSrc + k0);
                rb1 = *(const uint4*)(bSrc + k0 + 8);
            }
        }

        const uint32_t aH = smA + (uint32_t)cur * 12288;
        const uint32_t aL = aH + 6144;
        const uint32_t bH = smB + (uint32_t)cur * 6144;

        uint32_t fbh[2][4];
        ldm_x4(fbh[0], bH + boff);
        ldm_x4(fbh[1], bH + boff + 16*STRB*2);

        #pragma unroll
        for (int mi = 0; mi < 4; ++mi) {
            uint32_t fah[4], fal[4];
            ldm_x4(fah, aH + aoff + mi * 16*STRB*2);
            ldm_x4(fal, aL + aoff + mi * 16*STRB*2);
            #pragma unroll
            for (int nj = 0; nj < 4; ++nj) {
                int t = nj >> 1, s = nj & 1;
                float* c = acc[mi][nj];
                mma16816(c, fah, fbh[t][s], fbh[t][s+2]);
                mma16816(c, fal, fbh[t][s], fbh[t][s+2]);
            }
        }

        if (kt < 63) {
            uint4* dA = (uint4*)&sA[cur ^ 1][lhalf][lrow * STRB];
            dA[0] = ra0; dA[1] = ra1;
            if (lhalf == 0) {
                uint4* dB = (uint4*)&sB[cur ^ 1][lrow * STRB];
                dB[0] = rb0; dB[1] = rb1;
            }
            __syncthreads();
        }
    }

    // epilogue
    const int group = lane >> 2, tig = lane & 3;
    #pragma unroll
    for (int mi = 0; mi < 4; ++mi) {
        #pragma unroll
        for (int nj = 0; nj < 4; ++nj) {
            int nl = wn*32 + nj*8 + tig*2;
            int c  = n0 + nl;
            int g  = c >> 8, cc = c & 255;
            int hh = r + 4 * (cc >> 6), d = cc & 63;
            const float* barr = (g == 0) ? bq : (g == 1) ? bkv : bkv + 1024;
            float b0v = barr[hh*64 + d], b1v = barr[hh*64 + d + 1];
            #pragma unroll
            for (int half = 0; half < 2; ++half) {
                int jrow = m0 + wm*64 + mi*16 + group + half*8;
                int seg = jrow >> 9, p = jrow & 511;
                float vx = acc[mi][nj][half*2 + 0] + b0v;
                float vy = acc[mi][nj][half*2 + 1] + b1v;
                long bsh = (long)((b*NSEG + seg)*NHEAD + hh);
                if (g == 0) {
                    vx *= 0.125f; vy *= 0.125f;
                    uint32_t hi, lo;
                    pack_hl(vx, vy, hi, lo);
                    long idx = (bsh*NPTS + p)*DHEAD + d;
                    *(uint32_t*)&g_Qh[idx] = hi;
                    *(uint32_t*)&g_Ql[idx] = lo;
                } else if (g == 1) {
                    __half2 hv; hv.x = __float2half_rn(vx); hv.y = __float2half_rn(vy);
                    long idx = (bsh*NPTS + p)*DHEAD + d;
                    *(__half2*)&g_Kh[idx] = hv;
                } else {
                    __half hx = __float2half_rn(vx), hy = __float2half_rn(vy);
                    __half lx = __float2half_rn(vx - __half2float(hx));
                    __half ly = __float2half_rn(vy - __half2float(hy));
                    long idx = (bsh*DHEAD + d)*NPTS + p;
                    g_Vth[idx] = hx; g_Vth[idx + NPTS] = hy;
                    g_Vtl[idx] = lx; g_Vtl[idx + NPTS] = ly;
                }
            }
        }
    }
}

// ---------------------------------------------------------------------------
// Flash attention fp16: S = (Qh+Ql)Kh; O = Ph(Vh+Vl)  (Pl dropped).
// ---------------------------------------------------------------------------
#define BUFE (192*STR)
#define QOFF (2*BUFE)

__global__ __launch_bounds__(256) void attn_mma(float* __restrict__ out)
{
    extern __shared__ __half sbm[];
    const int tid = threadIdx.x;
    const int lane = tid & 31, warp = tid >> 5;
    const int qt = blockIdx.x, h = blockIdx.y, bs = blockIdx.z;
    const int b = bs >> 2, seg = bs & 3;
    const long base = (long)(bs*NHEAD + h) * (NPTS*DHEAD);

    const uint32_t sm0 = (uint32_t)__cvta_generic_to_shared(sbm);

    const int lm = tid / 64, lj = tid & 63;
    const bool ldr = tid < 192;
    const __half* csrc = nullptr;
    long cstep = 0;
    uint32_t cdst = 0;
    if (ldr) {
        if      (lm == 0) { csrc = g_Kh  + base + lj*DHEAD;      cstep = 64*DHEAD; }
        else if (lm == 1) { csrc = g_Vth + base + (long)lj*NPTS; cstep = 64; }
        else              { csrc = g_Vtl + base + (long)lj*NPTS; cstep = 64; }
        cdst = sm0 + (uint32_t)((lm*64 + lj)*STR)*2;
    }

    {
        int qhf = tid >> 7, qrow = tid & 127;
        const __half* qs = (qhf ? g_Ql : g_Qh) + base + (long)(qt*128 + qrow)*DHEAD;
        uint32_t qd = sm0 + (uint32_t)(QOFF + (qhf*128 + qrow)*STR)*2;
        #pragma unroll
        for (int i = 0; i < 8; ++i) cp16(qd + i*16, qs + i*8);
        if (ldr) {
            #pragma unroll
            for (int i = 0; i < 8; ++i) cp16(cdst + i*16, csrc + i*8);
        }
    }
    cp_commit();
    cp_waitall();
    __syncthreads();

    const int lrow16 = (lane & 7) + ((lane >> 3) & 1) * 8;
    const int kbyt   = (lane >> 4) * 16;

    uint32_t qh[4][4], ql[4][4];
    {
        uint32_t qa = sm0 + (uint32_t)(QOFF + (warp*16 + lrow16)*STR)*2 + kbyt;
        #pragma unroll
        for (int kk = 0; kk < 4; ++kk) {
            ldm_x4(qh[kk], qa + kk*32);
            ldm_x4(ql[kk], qa + 128*STR*2 + kk*32);
        }
    }
    if (ldr) {
        const __half* s = csrc + cstep;
        uint32_t d = cdst + (uint32_t)BUFE*2;
        #pragma unroll
        for (int i = 0; i < 8; ++i) cp16(d + i*16, s + i*8);
    }
    cp_commit();

    float m0 = -1e30f, m1 = -1e30f, l0 = 0.f, l1 = 0.f;
    float o[8][4];
    #pragma unroll
    for (int j = 0; j < 8; ++j)
        #pragma unroll
        for (int q = 0; q < 4; ++q) o[j][q] = 0.f;

    for (int ck = 0; ck < 8; ++ck) {
        const uint32_t sK  = sm0 + (uint32_t)(ck & 1)*BUFE*2;
        const uint32_t sV  = sK + 64*STR*2;
        const uint32_t sVl = sK + 128*STR*2;

        float sc[8][4];
        #pragma unroll
        for (int j = 0; j < 8; ++j)
            #pragma unroll
            for (int q = 0; q < 4; ++q) sc[j][q] = 0.f;

        #pragma unroll
        for (int kk = 0; kk < 4; ++kk) {
            uint32_t kbh[4][4];
            #pragma unroll
            for (int kg = 0; kg < 4; ++kg) {
                uint32_t a = (uint32_t)((kg*16 + lrow16)*STR*2 + kk*32 + kbyt);
                ldm_x4(kbh[kg], sK + a);
            }
            #pragma unroll
            for (int kg = 0; kg < 4; ++kg)
                #pragma unroll
                for (int s = 0; s < 2; ++s) {
                    float* c = sc[kg*2 + s];
                    mma16816(c, qh[kk], kbh[kg][s], kbh[kg][s+2]);
                    mma16816(c, ql[kk], kbh[kg][s], kbh[kg][s+2]);
                }
        }

        float mc0 = -1e30f, mc1 = -1e30f;
        #pragma unroll
        for (int j = 0; j < 8; ++j) {
            mc0 = fmaxf(mc0, fmaxf(sc[j][0], sc[j][1]));
            mc1 = fmaxf(mc1, fmaxf(sc[j][2], sc[j][3]));
        }
        mc0 = fmaxf(mc0, __shfl_xor_sync(0xffffffffu, mc0, 1));
        mc0 = fmaxf(mc0, __shfl_xor_sync(0xffffffffu, mc0, 2));
        mc1 = fmaxf(mc1, __shfl_xor_sync(0xffffffffu, mc1, 1));
        mc1 = fmaxf(mc1, __shfl_xor_sync(0xffffffffu, mc1, 2));
        float mn0 = fmaxf(m0, mc0), mn1 = fmaxf(m1, mc1);
        float a0 = __expf(m0 - mn0), a1 = __expf(m1 - mn1);
        float s0 = 0.f, s1 = 0.f;
        #pragma unroll
        for (int j = 0; j < 8; ++j) {
            sc[j][0] = __expf(sc[j][0] - mn0);
            sc[j][1] = __expf(sc[j][1] - mn0);
            sc[j][2] = __expf(sc[j][2] - mn1);
            sc[j][3] = __expf(sc[j][3] - mn1);
            s0 += sc[j][0] + sc[j][1];
            s1 += sc[j][2] + sc[j][3];
        }
        s0 += __shfl_xor_sync(0xffffffffu, s0, 1);
        s0 += __shfl_xor_sync(0xffffffffu, s0, 2);
        s1 += __shfl_xor_sync(0xffffffffu, s1, 1);
        s1 += __shfl_xor_sync(0xffffffffu, s1, 2);
        l0 = l0*a0 + s0; l1 = l1*a1 + s1;
        m0 = mn0; m1 = mn1;
        #pragma unroll
        for (int j = 0; j < 8; ++j) {
            o[j][0] *= a0; o[j][1] *= a0;
            o[j][2] *= a1; o[j][3] *= a1;
        }

        // P -> A-frags (hi only; Pl dropped)
        uint32_t ph[4][4];
        #pragma unroll
        for (int t = 0; t < 4; ++t) {
            ph[t][0] = pack_h(sc[2*t  ][0], sc[2*t  ][1]);
            ph[t][1] = pack_h(sc[2*t  ][2], sc[2*t  ][3]);
            ph[t][2] = pack_h(sc[2*t+1][0], sc[2*t+1][1]);
            ph[t][3] = pack_h(sc[2*t+1][2], sc[2*t+1][3]);
        }

        // O += Ph (Vh + Vl)
        #pragma unroll
        for (int t = 0; t < 4; ++t) {
            uint32_t vbh[4][4], vbl[4][4];
            #pragma unroll
            for (int nt = 0; nt < 4; ++nt) {
                uint32_t a = (uint32_t)((nt*16 + lrow16)*STR*2 + t*32 + kbyt);
                ldm_x4(vbh[nt], sV + a);
                ldm_x4(vbl[nt], sVl + a);
            }
            #pragma unroll
            for (int nt = 0; nt < 4; ++nt)
                #pragma unroll
                for (int s = 0; s < 2; ++s) {
                    float* c = o[nt*2 + s];
                    mma16816(c, ph[t], vbh[nt][s], vbh[nt][s+2]);
                    mma16816(c, ph[t], vbl[nt][s], vbl[nt][s+2]);
                }
        }

        cp_waitall();
        __syncthreads();
        if (ck + 2 < 8 && ldr) {
            const __half* s = csrc + (long)(ck + 2)*cstep;
            uint32_t d = cdst + (uint32_t)(ck & 1)*BUFE*2;
            #pragma unroll
            for (int i = 0; i < 8; ++i) cp16(d + i*16, s + i*8);
        }
        if (ck + 2 < 8) cp_commit();
    }

    // epilogue
    float inv0 = 1.f / l0, inv1 = 1.f / l1;
    int r0 = lane >> 2, dc = (lane & 3) * 2;
    int p0 = qt*128 + warp*16 + r0;
    int s0p = seg*WSEG + 4*p0 + (h & 3);
    int s1p = s0p + 32;
    float* ob0 = out + ((long)b*SLEN + s0p)*HID + h*DHEAD + dc;
    float* ob1 = out + ((long)b*SLEN + s1p)*HID + h*DHEAD + dc;
    #pragma unroll
    for (int j = 0; j < 8; ++j) {
        float2 v0 = make_float2(o[j][0]*inv0, o[j][1]*inv0);
        float2 v1 = make_float2(o[j][2]*inv1, o[j][3]*inv1);
        *(float2*)(ob0 + j*8) = v0;
        *(float2*)(ob1 + j*8) = v1;
    }
}

// ---------------------------------------------------------------------------
extern "C" void kernel_launch(void* const* d_in, const int* in_sizes, int n_in,
                              void* d_out, int out_size)
{
    const float* X   = (const float*)d_in[0];
    const float* Wq  = (const float*)d_in[1];
    const float* bq  = (const float*)d_in[2];
    const float* Wkv = (const float*)d_in[3];
    const float* bkv = (const float*)d_in[4];
    float* out = (float*)d_out;

    cudaMemsetAsync(out, 0, (size_t)out_size * sizeof(float), 0);

    splitx<<<BATCH*SLEN*HID/4/256, 256>>>((const float4*)X);

    dim3 gw(HID/32, NCOL/32, 4);
    wpack<<<gw, 256>>>(Wq, Wkv);

    dim3 g1(NCOL/128, 16, BATCH * 4);
    proj_mma<<<g1, 256>>>(bq, bkv);

    const int smem = (2*BUFE + 256*STR) * (int)sizeof(__half);   // 92160 B
    cudaFuncSetAttribute(attn_mma, cudaFuncAttributeMaxDynamicSharedMemorySize, smem);
    dim3 g2(4, NHEAD, BATCH * NSEG);
    attn_mma<<<g2, 256, smem>>>(out);
}

// round 12
// speedup vs baseline: 1.6702x; 1.2956x over previous
#include <cuda_runtime.h>
#include <cuda_fp16.h>
#include <cstdint>

#define BATCH 2
#define SLEN  8192
#define HID   1024
#define NSEG  4
#define NPTS  512
#define NHEAD 16
#define DHEAD 64
#define WSEG  2048
#define NCOL  768
#define STRB  24   // proj smem stride (fp16)
#define STR   72   // attn smem stride (fp16)

#define GSIZE (BATCH*NSEG*NHEAD*NPTS*DHEAD)
__device__ __align__(16) __half g_Xh[BATCH*SLEN*HID];         // X rounded to fp16
__device__ __align__(16) __half g_Wp[4*NCOL*HID];             // [r][n][k] hi only
__device__ __align__(16) __half g_Qh[GSIZE], g_Ql[GSIZE];     // [b][seg][h][p][d], pre-scaled
__device__ __align__(16) __half g_Kh[GSIZE];                  // [b][seg][h][p][d]
__device__ __align__(16) __half g_Vth[GSIZE], g_Vtl[GSIZE];   // [b][seg][h][d][p]

// ---------------------------------------------------------------------------
__device__ __forceinline__ void ldm_x4(uint32_t* r, uint32_t addr) {
    asm volatile("ldmatrix.sync.aligned.m8n8.x4.shared.b16 {%0,%1,%2,%3}, [%4];\n"
                 : "=r"(r[0]), "=r"(r[1]), "=r"(r[2]), "=r"(r[3]) : "r"(addr));
}
__device__ __forceinline__ void mma16816(float* c, const uint32_t* a,
                                         uint32_t b0, uint32_t b1) {
    asm volatile("mma.sync.aligned.m16n8k16.row.col.f32.f16.f16.f32 "
                 "{%0,%1,%2,%3}, {%4,%5,%6,%7}, {%8,%9}, {%0,%1,%2,%3};\n"
                 : "+f"(c[0]), "+f"(c[1]), "+f"(c[2]), "+f"(c[3])
                 : "r"(a[0]), "r"(a[1]), "r"(a[2]), "r"(a[3]), "r"(b0), "r"(b1));
}
__device__ __forceinline__ void cp16(uint32_t dst, const void* src) {
    asm volatile("cp.async.cg.shared.global [%0], [%1], 16;\n" :: "r"(dst), "l"(src));
}
__device__ __forceinline__ void cp_commit() { asm volatile("cp.async.commit_group;\n"); }
__device__ __forceinline__ void cp_waitall() { asm volatile("cp.async.wait_group 0;\n"); }

__device__ __forceinline__ void pack_hl(float x, float y, uint32_t& hi, uint32_t& lo) {
    __half hx = __float2half_rn(x), hy = __float2half_rn(y);
    __half lx = __float2half_rn(x - __half2float(hx));
    __half ly = __float2half_rn(y - __half2float(hy));
    __half2 h2; h2.x = hx; h2.y = hy;
    __half2 l2; l2.x = lx; l2.y = ly;
    hi = *(uint32_t*)&h2; lo = *(uint32_t*)&l2;
}
__device__ __forceinline__ uint32_t pack_h(float x, float y) {
    __half2 h2; h2.x = __float2half_rn(x); h2.y = __float2half_rn(y);
    return *(uint32_t*)&h2;
}

// ---------------------------------------------------------------------------
__global__ __launch_bounds__(256) void splitx(const float4* __restrict__ X4)
{
    long i = (long)blockIdx.x * 256 + threadIdx.x;
    float4 v = X4[i];
    __half2 h01, h23;
    h01.x = __float2half_rn(v.x); h01.y = __float2half_rn(v.y);
    h23.x = __float2half_rn(v.z); h23.y = __float2half_rn(v.w);
    __half2* H2 = (__half2*)g_Xh;
    H2[2*i] = h01; H2[2*i+1] = h23;
}

// ---------------------------------------------------------------------------
__global__ __launch_bounds__(256) void wpack(const float* __restrict__ Wq,
                                             const float* __restrict__ Wkv)
{
    __shared__ float s[32][33];
    int tx = threadIdx.x & 31, ty = threadIdx.x >> 5;
    int r = blockIdx.z;
    int n = blockIdx.y * 32 + tx;
    int g = n >> 8, cc = n & 255;
    int h = r + 4 * (cc >> 6), d = cc & 63;
    const float* src; long stride;
    if (g == 0)      { src = Wq  + h*64 + d;        stride = 1024; }
    else if (g == 1) { src = Wkv + h*64 + d;        stride = 2048; }
    else             { src = Wkv + 1024 + h*64 + d; stride = 2048; }
    #pragma unroll
    for (int i = 0; i < 4; ++i) {
        int k = blockIdx.x * 32 + ty + i * 8;
        s[ty + i*8][tx] = src[(long)k * stride];
    }
    __syncthreads();
    long rbase = (long)r * NCOL * HID;
    #pragma unroll
    for (int i = 0; i < 4; ++i) {
        int nl = ty + i * 8;
        float v = s[tx][nl];
        long idx = (long)(blockIdx.y * 32 + nl) * HID + blockIdx.x * 32 + tx;
        g_Wp[rbase + idx] = __float2half_rn(v);
    }
}

// ---------------------------------------------------------------------------
// proj: single-term fp16 mma  C = X16 @ W16.  128x128 tile, k16 double-buffered.
// ---------------------------------------------------------------------------
__global__ __launch_bounds__(256, 2) void proj_mma(const float* __restrict__ bq,
                                                   const float* __restrict__ bkv)
{
    __shared__ __half sA[2][128*STRB];
    __shared__ __half sB[2][128*STRB];

    const int tid  = threadIdx.x;
    const int lane = tid & 31, warp = tid >> 5;
    const int wm = warp >> 2, wn = warp & 3;
    const int b  = blockIdx.z >> 2;
    const int r  = blockIdx.z & 3;
    const int m0 = blockIdx.y * 128;
    const int n0 = blockIdx.x * 128;

    // loader: tid<128 -> A row tid; tid>=128 -> B row tid-128; 32B per kstep
    const int lrow = tid & 127;
    const bool isA = tid < 128;
    const __half* src = isA
        ? g_Xh + ((long)b * SLEN + (4*(m0 + lrow) + r)) * HID
        : g_Wp + ((long)r * NCOL + n0 + lrow) * HID;

    const int lrow16 = (lane & 7) + ((lane >> 3) & 1) * 8;
    const int kbyt   = (lane >> 4) * 16;
    const uint32_t smA = (uint32_t)__cvta_generic_to_shared(&sA[0][0]);
    const uint32_t smB = (uint32_t)__cvta_generic_to_shared(&sB[0][0]);
    const uint32_t aoff = (uint32_t)((wm*64 + lrow16) * STRB * 2 + kbyt);
    const uint32_t boff = (uint32_t)((wn*32 + lrow16) * STRB * 2 + kbyt);

    float acc[4][4][4];
    #pragma unroll
    for (int i = 0; i < 4; ++i)
        #pragma unroll
        for (int j = 0; j < 4; ++j)
            #pragma unroll
            for (int q = 0; q < 4; ++q) acc[i][j][q] = 0.f;

    uint4 r0 = *(const uint4*)(src + 0);
    uint4 r1 = *(const uint4*)(src + 8);
    {
        uint4* dst = isA ? (uint4*)&sA[0][lrow * STRB] : (uint4*)&sB[0][lrow * STRB];
        dst[0] = r0; dst[1] = r1;
    }
    __syncthreads();

    for (int kt = 0; kt < 64; ++kt) {
        const int cur = kt & 1;
        if (kt < 63) {
            int k0 = (kt + 1) * 16;
            r0 = *(const uint4*)(src + k0);
            r1 = *(const uint4*)(src + k0 + 8);
        }

        const uint32_t aH = smA + (uint32_t)cur * 6144;
        const uint32_t bH = smB + (uint32_t)cur * 6144;

        uint32_t fbh[2][4];
        ldm_x4(fbh[0], bH + boff);
        ldm_x4(fbh[1], bH + boff + 16*STRB*2);

        #pragma unroll
        for (int mi = 0; mi < 4; ++mi) {
            uint32_t fah[4];
            ldm_x4(fah, aH + aoff + mi * 16*STRB*2);
            #pragma unroll
            for (int nj = 0; nj < 4; ++nj) {
                int t = nj >> 1, s = nj & 1;
                mma16816(acc[mi][nj], fah, fbh[t][s], fbh[t][s+2]);
            }
        }

        if (kt < 63) {
            uint4* dst = isA ? (uint4*)&sA[cur ^ 1][lrow * STRB]
                             : (uint4*)&sB[cur ^ 1][lrow * STRB];
            dst[0] = r0; dst[1] = r1;
            __syncthreads();
        }
    }

    // epilogue
    const int group = lane >> 2, tig = lane & 3;
    #pragma unroll
    for (int mi = 0; mi < 4; ++mi) {
        #pragma unroll
        for (int nj = 0; nj < 4; ++nj) {
            int nl = wn*32 + nj*8 + tig*2;
            int c  = n0 + nl;
            int g  = c >> 8, cc = c & 255;
            int hh = r + 4 * (cc >> 6), d = cc & 63;
            const float* barr = (g == 0) ? bq : (g == 1) ? bkv : bkv + 1024;
            float b0v = barr[hh*64 + d], b1v = barr[hh*64 + d + 1];
            #pragma unroll
            for (int half = 0; half < 2; ++half) {
                int jrow = m0 + wm*64 + mi*16 + group + half*8;
                int seg = jrow >> 9, p = jrow & 511;
                float vx = acc[mi][nj][half*2 + 0] + b0v;
                float vy = acc[mi][nj][half*2 + 1] + b1v;
                long bsh = (long)((b*NSEG + seg)*NHEAD + hh);
                if (g == 0) {
                    vx *= 0.125f; vy *= 0.125f;
                    uint32_t hi, lo;
                    pack_hl(vx, vy, hi, lo);
                    long idx = (bsh*NPTS + p)*DHEAD + d;
                    *(uint32_t*)&g_Qh[idx] = hi;
                    *(uint32_t*)&g_Ql[idx] = lo;
                } else if (g == 1) {
                    __half2 hv; hv.x = __float2half_rn(vx); hv.y = __float2half_rn(vy);
                    long idx = (bsh*NPTS + p)*DHEAD + d;
                    *(__half2*)&g_Kh[idx] = hv;
                } else {
                    __half hx = __float2half_rn(vx), hy = __float2half_rn(vy);
                    __half lx = __float2half_rn(vx - __half2float(hx));
                    __half ly = __float2half_rn(vy - __half2float(hy));
                    long idx = (bsh*DHEAD + d)*NPTS + p;
                    g_Vth[idx] = hx; g_Vth[idx + NPTS] = hy;
                    g_Vtl[idx] = lx; g_Vtl[idx + NPTS] = ly;
                }
            }
        }
    }
}

// ---------------------------------------------------------------------------
// Flash attention fp16: S = (Qh+Ql)Kh; O = Ph(Vh+Vl).  (unchanged from R11)
// ---------------------------------------------------------------------------
#define BUFE (192*STR)
#define QOFF (2*BUFE)

__global__ __launch_bounds__(256) void attn_mma(float* __restrict__ out)
{
    extern __shared__ __half sbm[];
    const int tid = threadIdx.x;
    const int lane = tid & 31, warp = tid >> 5;
    const int qt = blockIdx.x, h = blockIdx.y, bs = blockIdx.z;
    const int b = bs >> 2, seg = bs & 3;
    const long base = (long)(bs*NHEAD + h) * (NPTS*DHEAD);

    const uint32_t sm0 = (uint32_t)__cvta_generic_to_shared(sbm);

    const int lm = tid / 64, lj = tid & 63;
    const bool ldr = tid < 192;
    const __half* csrc = nullptr;
    long cstep = 0;
    uint32_t cdst = 0;
    if (ldr) {
        if      (lm == 0) { csrc = g_Kh  + base + lj*DHEAD;      cstep = 64*DHEAD; }
        else if (lm == 1) { csrc = g_Vth + base + (long)lj*NPTS; cstep = 64; }
        else              { csrc = g_Vtl + base + (long)lj*NPTS; cstep = 64; }
        cdst = sm0 + (uint32_t)((lm*64 + lj)*STR)*2;
    }

    {
        int qhf = tid >> 7, qrow = tid & 127;
        const __half* qs = (qhf ? g_Ql : g_Qh) + base + (long)(qt*128 + qrow)*DHEAD;
        uint32_t qd = sm0 + (uint32_t)(QOFF + (qhf*128 + qrow)*STR)*2;
        #pragma unroll
        for (int i = 0; i < 8; ++i) cp16(qd + i*16, qs + i*8);
        if (ldr) {
            #pragma unroll
            for (int i = 0; i < 8; ++i) cp16(cdst + i*16, csrc + i*8);
        }
    }
    cp_commit();
    cp_waitall();
    __syncthreads();

    const int lrow16 = (lane & 7) + ((lane >> 3) & 1) * 8;
    const int kbyt   = (lane >> 4) * 16;

    uint32_t qh[4][4], ql[4][4];
    {
        uint32_t qa = sm0 + (uint32_t)(QOFF + (warp*16 + lrow16)*STR)*2 + kbyt;
        #pragma unroll
        for (int kk = 0; kk < 4; ++kk) {
            ldm_x4(qh[kk], qa + kk*32);
            ldm_x4(ql[kk], qa + 128*STR*2 + kk*32);
        }
    }
    if (ldr) {
        const __half* s = csrc + cstep;
        uint32_t d = cdst + (uint32_t)BUFE*2;
        #pragma unroll
        for (int i = 0; i < 8; ++i) cp16(d + i*16, s + i*8);
    }
    cp_commit();

    float m0 = -1e30f, m1 = -1e30f, l0 = 0.f, l1 = 0.f;
    float o[8][4];
    #pragma unroll
    for (int j = 0; j < 8; ++j)
        #pragma unroll
        for (int q = 0; q < 4; ++q) o[j][q] = 0.f;

    for (int ck = 0; ck < 8; ++ck) {
        const uint32_t sK  = sm0 + (uint32_t)(ck & 1)*BUFE*2;
        const uint32_t sV  = sK + 64*STR*2;
        const uint32_t sVl = sK + 128*STR*2;

        float sc[8][4];
        #pragma unroll
        for (int j = 0; j < 8; ++j)
            #pragma unroll
            for (int q = 0; q < 4; ++q) sc[j][q] = 0.f;

        #pragma unroll
        for (int kk = 0; kk < 4; ++kk) {
            uint32_t kbh[4][4];
            #pragma unroll
            for (int kg = 0; kg < 4; ++kg) {
                uint32_t a = (uint32_t)((kg*16 + lrow16)*STR*2 + kk*32 + kbyt);
                ldm_x4(kbh[kg], sK + a);
            }
            #pragma unroll
            for (int kg = 0; kg < 4; ++kg)
                #pragma unroll
                for (int s = 0; s < 2; ++s) {
                    float* c = sc[kg*2 + s];
                    mma16816(c, qh[kk], kbh[kg][s], kbh[kg][s+2]);
                    mma16816(c, ql[kk], kbh[kg][s], kbh[kg][s+2]);
                }
        }

        float mc0 = -1e30f, mc1 = -1e30f;
        #pragma unroll
        for (int j = 0; j < 8; ++j) {
            mc0 = fmaxf(mc0, fmaxf(sc[j][0], sc[j][1]));
            mc1 = fmaxf(mc1, fmaxf(sc[j][2], sc[j][3]));
        }
        mc0 = fmaxf(mc0, __shfl_xor_sync(0xffffffffu, mc0, 1));
        mc0 = fmaxf(mc0, __shfl_xor_sync(0xffffffffu, mc0, 2));
        mc1 = fmaxf(mc1, __shfl_xor_sync(0xffffffffu, mc1, 1));
        mc1 = fmaxf(mc1, __shfl_xor_sync(0xffffffffu, mc1, 2));
        float mn0 = fmaxf(m0, mc0), mn1 = fmaxf(m1, mc1);
        float a0 = __expf(m0 - mn0), a1 = __expf(m1 - mn1);
        float s0 = 0.f, s1 = 0.f;
        #pragma unroll
        for (int j = 0; j < 8; ++j) {
            sc[j][0] = __expf(sc[j][0] - mn0);
            sc[j][1] = __expf(sc[j][1] - mn0);
            sc[j][2] = __expf(sc[j][2] - mn1);
            sc[j][3] = __expf(sc[j][3] - mn1);
            s0 += sc[j][0] + sc[j][1];
            s1 += sc[j][2] + sc[j][3];
        }
        s0 += __shfl_xor_sync(0xffffffffu, s0, 1);
        s0 += __shfl_xor_sync(0xffffffffu, s0, 2);
        s1 += __shfl_xor_sync(0xffffffffu, s1, 1);
        s1 += __shfl_xor_sync(0xffffffffu, s1, 2);
        l0 = l0*a0 + s0; l1 = l1*a1 + s1;
        m0 = mn0; m1 = mn1;
        #pragma unroll
        for (int j = 0; j < 8; ++j) {
            o[j][0] *= a0; o[j][1] *= a0;
            o[j][2] *= a1; o[j][3] *= a1;
        }

        uint32_t ph[4][4];
        #pragma unroll
        for (int t = 0; t < 4; ++t) {
            ph[t][0] = pack_h(sc[2*t  ][0], sc[2*t  ][1]);
            ph[t][1] = pack_h(sc[2*t  ][2], sc[2*t  ][3]);
            ph[t][2] = pack_h(sc[2*t+1][0], sc[2*t+1][1]);
            ph[t][3] = pack_h(sc[2*t+1][2], sc[2*t+1][3]);
        }

        #pragma unroll
        for (int t = 0; t < 4; ++t) {
            uint32_t vbh[4][4], vbl[4][4];
            #pragma unroll
            for (int nt = 0; nt < 4; ++nt) {
                uint32_t a = (uint32_t)((nt*16 + lrow16)*STR*2 + t*32 + kbyt);
                ldm_x4(vbh[nt], sV + a);
                ldm_x4(vbl[nt], sVl + a);
            }
            #pragma unroll
            for (int nt = 0; nt < 4; ++nt)
                #pragma unroll
                for (int s = 0; s < 2; ++s) {
                    float* c = o[nt*2 + s];
                    mma16816(c, ph[t], vbh[nt][s], vbh[nt][s+2]);
                    mma16816(c, ph[t], vbl[nt][s], vbl[nt][s+2]);
                }
        }

        cp_waitall();
        __syncthreads();
        if (ck + 2 < 8 && ldr) {
            const __half* s = csrc + (long)(ck + 2)*cstep;
            uint32_t d = cdst + (uint32_t)(ck & 1)*BUFE*2;
            #pragma unroll
            for (int i = 0; i < 8; ++i) cp16(d + i*16, s + i*8);
        }
        if (ck + 2 < 8) cp_commit();
    }

    float inv0 = 1.f / l0, inv1 = 1.f / l1;
    int r0 = lane >> 2, dc = (lane & 3) * 2;
    int p0 = qt*128 + warp*16 + r0;
    int s0p = seg*WSEG + 4*p0 + (h & 3);
    int s1p = s0p + 32;
    float* ob0 = out + ((long)b*SLEN + s0p)*HID + h*DHEAD + dc;
    float* ob1 = out + ((long)b*SLEN + s1p)*HID + h*DHEAD + dc;
    #pragma unroll
    for (int j = 0; j < 8; ++j) {
        float2 v0 = make_float2(o[j][0]*inv0, o[j][1]*inv0);
        float2 v1 = make_float2(o[j][2]*inv1, o[j][3]*inv1);
        *(float2*)(ob0 + j*8) = v0;
        *(float2*)(ob1 + j*8) = v1;
    }
}

// ---------------------------------------------------------------------------
extern "C" void kernel_launch(void* const* d_in, const int* in_sizes, int n_in,
                              void* d_out, int out_size)
{
    const float* X   = (const float*)d_in[0];
    const float* Wq  = (const float*)d_in[1];
    const float* bq  = (const float*)d_in[2];
    const float* Wkv = (const float*)d_in[3];
    const float* bkv = (const float*)d_in[4];
    float* out = (float*)d_out;

    cudaMemsetAsync(out, 0, (size_t)out_size * sizeof(float), 0);

    splitx<<<BATCH*SLEN*HID/4/256, 256>>>((const float4*)X);

    dim3 gw(HID/32, NCOL/32, 4);
    wpack<<<gw, 256>>>(Wq, Wkv);

    dim3 g1(NCOL/128, 16, BATCH * 4);
    proj_mma<<<g1, 256>>>(bq, bkv);

    const int smem = (2*BUFE + 256*STR) * (int)sizeof(__half);   // 92160 B
    cudaFuncSetAttribute(attn_mma, cudaFuncAttributeMaxDynamicSharedMemorySize, smem);
    dim3 g2(4, NHEAD, BATCH * NSEG);
    attn_mma<<<g2, 256, smem>>>(out);
}

// round 15
// speedup vs baseline: 1.9439x; 1.1639x over previous
#include <cuda_runtime.h>
#include <cuda_fp16.h>
#include <cstdint>

#define BATCH 2
#define SLEN  8192
#define HID   1024
#define NSEG  4
#define NPTS  512
#define NHEAD 16
#define DHEAD 64
#define WSEG  2048
#define NCOL  768
#define STRB  24   // proj smem stride (fp16)
#define STR   72   // attn smem stride (fp16)

#define GSIZE (BATCH*NSEG*NHEAD*NPTS*DHEAD)
__device__ __align__(16) __half g_Xh[BATCH*SLEN*HID];         // X rounded to fp16
__device__ __align__(16) __half g_Wp[4*NCOL*HID];             // [r][n][k]
__device__ __align__(16) __half g_Qh[GSIZE];                  // [b][seg][h][p][d], pre-scaled
__device__ __align__(16) __half g_Kh[GSIZE];                  // [b][seg][h][p][d]
__device__ __align__(16) __half g_Vth[GSIZE];                 // [b][seg][h][d][p]

// ---------------------------------------------------------------------------
__device__ __forceinline__ void ldm_x4(uint32_t* r, uint32_t addr) {
    asm volatile("ldmatrix.sync.aligned.m8n8.x4.shared.b16 {%0,%1,%2,%3}, [%4];\n"
                 : "=r"(r[0]), "=r"(r[1]), "=r"(r[2]), "=r"(r[3]) : "r"(addr));
}
__device__ __forceinline__ void mma16816(float* c, const uint32_t* a,
                                         uint32_t b0, uint32_t b1) {
    asm volatile("mma.sync.aligned.m16n8k16.row.col.f32.f16.f16.f32 "
                 "{%0,%1,%2,%3}, {%4,%5,%6,%7}, {%8,%9}, {%0,%1,%2,%3};\n"
                 : "+f"(c[0]), "+f"(c[1]), "+f"(c[2]), "+f"(c[3])
                 : "r"(a[0]), "r"(a[1]), "r"(a[2]), "r"(a[3]), "r"(b0), "r"(b1));
}
__device__ __forceinline__ void cp16(uint32_t dst, const void* src) {
    asm volatile("cp.async.cg.shared.global [%0], [%1], 16;\n" :: "r"(dst), "l"(src));
}
__device__ __forceinline__ void cp_commit() { asm volatile("cp.async.commit_group;\n"); }
__device__ __forceinline__ void cp_waitall() { asm volatile("cp.async.wait_group 0;\n"); }

__device__ __forceinline__ uint32_t pack_h(float x, float y) {
    __half2 h2; h2.x = __float2half_rn(x); h2.y = __float2half_rn(y);
    return *(uint32_t*)&h2;
}

// ---------------------------------------------------------------------------
__global__ __launch_bounds__(256) void splitx(const float4* __restrict__ X4)
{
    long i = (long)blockIdx.x * 256 + threadIdx.x;
    float4 v = X4[i];
    __half2 h01, h23;
    h01.x = __float2half_rn(v.x); h01.y = __float2half_rn(v.y);
    h23.x = __float2half_rn(v.z); h23.y = __float2half_rn(v.w);
    __half2* H2 = (__half2*)g_Xh;
    H2[2*i] = h01; H2[2*i+1] = h23;
}

// ---------------------------------------------------------------------------
__global__ __launch_bounds__(256) void wpack(const float* __restrict__ Wq,
                                             const float* __restrict__ Wkv)
{
    __shared__ float s[32][33];
    int tx = threadIdx.x & 31, ty = threadIdx.x >> 5;
    int r = blockIdx.z;
    int n = blockIdx.y * 32 + tx;
    int g = n >> 8, cc = n & 255;
    int h = r + 4 * (cc >> 6), d = cc & 63;
    const float* src; long stride;
    if (g == 0)      { src = Wq  + h*64 + d;        stride = 1024; }
    else if (g == 1) { src = Wkv + h*64 + d;        stride = 2048; }
    else             { src = Wkv + 1024 + h*64 + d; stride = 2048; }
    #pragma unroll
    for (int i = 0; i < 4; ++i) {
        int k = blockIdx.x * 32 + ty + i * 8;
        s[ty + i*8][tx] = src[(long)k * stride];
    }
    __syncthreads();
    long rbase = (long)r * NCOL * HID;
    #pragma unroll
    for (int i = 0; i < 4; ++i) {
        int nl = ty + i * 8;
        float v = s[tx][nl];
        long idx = (long)(blockIdx.y * 32 + nl) * HID + blockIdx.x * 32 + tx;
        g_Wp[rbase + idx] = __float2half_rn(v);
    }
}

// ---------------------------------------------------------------------------
// proj: single-term fp16 mma  C = X16 @ W16.  128x128 tile, k16 double-buffered.
// ---------------------------------------------------------------------------
__global__ __launch_bounds__(256, 2) void proj_mma(const float* __restrict__ bq,
                                                   const float* __restrict__ bkv)
{
    __shared__ __half sA[2][128*STRB];
    __shared__ __half sB[2][128*STRB];

    const int tid  = threadIdx.x;
    const int lane = tid & 31, warp = tid >> 5;
    const int wm = warp >> 2, wn = warp & 3;
    const int b  = blockIdx.z >> 2;
    const int r  = blockIdx.z & 3;
    const int m0 = blockIdx.y * 128;
    const int n0 = blockIdx.x * 128;

    const int lrow = tid & 127;
    const bool isA = tid < 128;
    const __half* src = isA
        ? g_Xh + ((long)b * SLEN + (4*(m0 + lrow) + r)) * HID
        : g_Wp + ((long)r * NCOL + n0 + lrow) * HID;

    const int lrow16 = (lane & 7) + ((lane >> 3) & 1) * 8;
    const int kbyt   = (lane >> 4) * 16;
    const uint32_t smA = (uint32_t)__cvta_generic_to_shared(&sA[0][0]);
    const uint32_t smB = (uint32_t)__cvta_generic_to_shared(&sB[0][0]);
    const uint32_t aoff = (uint32_t)((wm*64 + lrow16) * STRB * 2 + kbyt);
    const uint32_t boff = (uint32_t)((wn*32 + lrow16) * STRB * 2 + kbyt);

    float acc[4][4][4];
    #pragma unroll
    for (int i = 0; i < 4; ++i)
        #pragma unroll
        for (int j = 0; j < 4; ++j)
            #pragma unroll
            for (int q = 0; q < 4; ++q) acc[i][j][q] = 0.f;

    uint4 r0 = *(const uint4*)(src + 0);
    uint4 r1 = *(const uint4*)(src + 8);
    {
        uint4* dst = isA ? (uint4*)&sA[0][lrow * STRB] : (uint4*)&sB[0][lrow * STRB];
        dst[0] = r0; dst[1] = r1;
    }
    __syncthreads();

    for (int kt = 0; kt < 64; ++kt) {
        const int cur = kt & 1;
        if (kt < 63) {
            int k0 = (kt + 1) * 16;
            r0 = *(const uint4*)(src + k0);
            r1 = *(const uint4*)(src + k0 + 8);
        }

        const uint32_t aH = smA + (uint32_t)cur * 6144;
        const uint32_t bH = smB + (uint32_t)cur * 6144;

        uint32_t fbh[2][4];
        ldm_x4(fbh[0], bH + boff);
        ldm_x4(fbh[1], bH + boff + 16*STRB*2);

        #pragma unroll
        for (int mi = 0; mi < 4; ++mi) {
            uint32_t fah[4];
            ldm_x4(fah, aH + aoff + mi * 16*STRB*2);
            #pragma unroll
            for (int nj = 0; nj < 4; ++nj) {
                int t = nj >> 1, s = nj & 1;
                mma16816(acc[mi][nj], fah, fbh[t][s], fbh[t][s+2]);
            }
        }

        if (kt < 63) {
            uint4* dst = isA ? (uint4*)&sA[cur ^ 1][lrow * STRB]
                             : (uint4*)&sB[cur ^ 1][lrow * STRB];
            dst[0] = r0; dst[1] = r1;
            __syncthreads();
        }
    }

    // epilogue (all outputs single fp16; Q pre-scaled, V transposed)
    const int group = lane >> 2, tig = lane & 3;
    #pragma unroll
    for (int mi = 0; mi < 4; ++mi) {
        #pragma unroll
        for (int nj = 0; nj < 4; ++nj) {
            int nl = wn*32 + nj*8 + tig*2;
            int c  = n0 + nl;
            int g  = c >> 8, cc = c & 255;
            int hh = r + 4 * (cc >> 6), d = cc & 63;
            const float* barr = (g == 0) ? bq : (g == 1) ? bkv : bkv + 1024;
            float b0v = barr[hh*64 + d], b1v = barr[hh*64 + d + 1];
            #pragma unroll
            for (int half = 0; half < 2; ++half) {
                int jrow = m0 + wm*64 + mi*16 + group + half*8;
                int seg = jrow >> 9, p = jrow & 511;
                float vx = acc[mi][nj][half*2 + 0] + b0v;
                float vy = acc[mi][nj][half*2 + 1] + b1v;
                long bsh = (long)((b*NSEG + seg)*NHEAD + hh);
                if (g == 0) {
                    long idx = (bsh*NPTS + p)*DHEAD + d;
                    *(uint32_t*)&g_Qh[idx] = pack_h(vx * 0.125f, vy * 0.125f);
                } else if (g == 1) {
                    long idx = (bsh*NPTS + p)*DHEAD + d;
                    *(uint32_t*)&g_Kh[idx] = pack_h(vx, vy);
                } else {
                    long idx = (bsh*DHEAD + d)*NPTS + p;
                    g_Vth[idx]        = __float2half_rn(vx);
                    g_Vth[idx + NPTS] = __float2half_rn(vy);
                }
            }
        }
    }
}

// ---------------------------------------------------------------------------
// Flash attention fp16, single-plane: S = Qh Kh; O = Ph Vh.
// Chunk buf: K(64 rows) + Vt(64 rows); Q zone 128 rows.  2 CTAs/SM.
// ---------------------------------------------------------------------------
#define BUFE (128*STR)
#define QOFF (2*BUFE)

__global__ __launch_bounds__(256, 2) void attn_mma(float* __restrict__ out)
{
    extern __shared__ __half sbm[];
    const int tid = threadIdx.x;
    const int lane = tid & 31, warp = tid >> 5;
    const int qt = blockIdx.x, h = blockIdx.y, bs = blockIdx.z;
    const int b = bs >> 2, seg = bs & 3;
    const long base = (long)(bs*NHEAD + h) * (NPTS*DHEAD);

    const uint32_t sm0 = (uint32_t)__cvta_generic_to_shared(sbm);

    // chunk loader: 256 threads, half-row (64B) each over 128 rows
    const int crow = tid >> 1, chalf = tid & 1;
    const int lm = crow >> 6, lj = crow & 63;
    const __half* csrc = (lm == 0)
        ? g_Kh  + base + lj*DHEAD + chalf*32
        : g_Vth + base + (long)lj*NPTS + chalf*32;
    const long cstep = (lm == 0) ? 64*DHEAD : 64;
    const uint32_t cdst = sm0 + (uint32_t)((lm*64 + lj)*STR)*2 + (uint32_t)chalf*64;

    // stage Q (128 rows, half-row per thread) + chunk0
    {
        int qrow = tid >> 1, qhalf = tid & 1;
        const __half* qs = g_Qh + base + (long)(qt*128 + qrow)*DHEAD + qhalf*32;
        uint32_t qd = sm0 + (uint32_t)(QOFF + qrow*STR)*2 + (uint32_t)qhalf*64;
        #pragma unroll
        for (int i = 0; i < 4; ++i) cp16(qd + i*16, qs + i*8);
        #pragma unroll
        for (int i = 0; i < 4; ++i) cp16(cdst + i*16, csrc + i*8);
    }
    cp_commit();
    cp_waitall();
    __syncthreads();

    const int lrow16 = (lane & 7) + ((lane >> 3) & 1) * 8;
    const int kbyt   = (lane >> 4) * 16;

    uint32_t qh[4][4];
    {
        uint32_t qa = sm0 + (uint32_t)(QOFF + (warp*16 + lrow16)*STR)*2 + kbyt;
        #pragma unroll
        for (int kk = 0; kk < 4; ++kk) ldm_x4(qh[kk], qa + kk*32);
    }
    // chunk1 -> buf1
    {
        const __half* s = csrc + cstep;
        uint32_t d = cdst + (uint32_t)BUFE*2;
        #pragma unroll
        for (int i = 0; i < 4; ++i) cp16(d + i*16, s + i*8);
    }
    cp_commit();

    float m0 = -1e30f, m1 = -1e30f, l0 = 0.f, l1 = 0.f;
    float o[8][4];
    #pragma unroll
    for (int j = 0; j < 8; ++j)
        #pragma unroll
        for (int q = 0; q < 4; ++q) o[j][q] = 0.f;

    for (int ck = 0; ck < 8; ++ck) {
        const uint32_t sK = sm0 + (uint32_t)(ck & 1)*BUFE*2;
        const uint32_t sV = sK + 64*STR*2;

        float sc[8][4];
        #pragma unroll
        for (int j = 0; j < 8; ++j)
            #pragma unroll
            for (int q = 0; q < 4; ++q) sc[j][q] = 0.f;

        #pragma unroll
        for (int kk = 0; kk < 4; ++kk) {
            uint32_t kbh[4][4];
            #pragma unroll
            for (int kg = 0; kg < 4; ++kg) {
                uint32_t a = (uint32_t)((kg*16 + lrow16)*STR*2 + kk*32 + kbyt);
                ldm_x4(kbh[kg], sK + a);
            }
            #pragma unroll
            for (int kg = 0; kg < 4; ++kg)
                #pragma unroll
                for (int s = 0; s < 2; ++s)
                    mma16816(sc[kg*2 + s], qh[kk], kbh[kg][s], kbh[kg][s+2]);
        }

        float mc0 = -1e30f, mc1 = -1e30f;
        #pragma unroll
        for (int j = 0; j < 8; ++j) {
            mc0 = fmaxf(mc0, fmaxf(sc[j][0], sc[j][1]));
            mc1 = fmaxf(mc1, fmaxf(sc[j][2], sc[j][3]));
        }
        mc0 = fmaxf(mc0, __shfl_xor_sync(0xffffffffu, mc0, 1));
        mc0 = fmaxf(mc0, __shfl_xor_sync(0xffffffffu, mc0, 2));
        mc1 = fmaxf(mc1, __shfl_xor_sync(0xffffffffu, mc1, 1));
        mc1 = fmaxf(mc1, __shfl_xor_sync(0xffffffffu, mc1, 2));
        float mn0 = fmaxf(m0, mc0), mn1 = fmaxf(m1, mc1);
        float a0 = __expf(m0 - mn0), a1 = __expf(m1 - mn1);
        float s0 = 0.f, s1 = 0.f;
        #pragma unroll
        for (int j = 0; j < 8; ++j) {
            sc[j][0] = __expf(sc[j][0] - mn0);
            sc[j][1] = __expf(sc[j][1] - mn0);
            sc[j][2] = __expf(sc[j][2] - mn1);
            sc[j][3] = __expf(sc[j][3] - mn1);
            s0 += sc[j][0] + sc[j][1];
            s1 += sc[j][2] + sc[j][3];
        }
        s0 += __shfl_xor_sync(0xffffffffu, s0, 1);
        s0 += __shfl_xor_sync(0xffffffffu, s0, 2);
        s1 += __shfl_xor_sync(0xffffffffu, s1, 1);
        s1 += __shfl_xor_sync(0xffffffffu, s1, 2);
        l0 = l0*a0 + s0; l1 = l1*a1 + s1;
        m0 = mn0; m1 = mn1;
        #pragma unroll
        for (int j = 0; j < 8; ++j) {
            o[j][0] *= a0; o[j][1] *= a0;
            o[j][2] *= a1; o[j][3] *= a1;
        }

        uint32_t ph[4][4];
        #pragma unroll
        for (int t = 0; t < 4; ++t) {
            ph[t][0] = pack_h(sc[2*t  ][0], sc[2*t  ][1]);
            ph[t][1] = pack_h(sc[2*t  ][2], sc[2*t  ][3]);
            ph[t][2] = pack_h(sc[2*t+1][0], sc[2*t+1][1]);
            ph[t][3] = pack_h(sc[2*t+1][2], sc[2*t+1][3]);
        }

        #pragma unroll
        for (int t = 0; t < 4; ++t) {
            uint32_t vbh[4][4];
            #pragma unroll
            for (int nt = 0; nt < 4; ++nt) {
                uint32_t a = (uint32_t)((nt*16 + lrow16)*STR*2 + t*32 + kbyt);
                ldm_x4(vbh[nt], sV + a);
            }
            #pragma unroll
            for (int nt = 0; nt < 4; ++nt)
                #pragma unroll
                for (int s = 0; s < 2; ++s)
                    mma16816(o[nt*2 + s], ph[t], vbh[nt][s], vbh[nt][s+2]);
        }

        cp_waitall();
        __syncthreads();
        if (ck + 2 < 8) {
            const __half* s = csrc + (long)(ck + 2)*cstep;
            uint32_t d = cdst + (uint32_t)(ck & 1)*BUFE*2;
            #pragma unroll
            for (int i = 0; i < 4; ++i) cp16(d + i*16, s + i*8);
            cp_commit();
        }
    }

    // epilogue
    float inv0 = 1.f / l0, inv1 = 1.f / l1;
    int r0 = lane >> 2, dc = (lane & 3) * 2;
    int p0 = qt*128 + warp*16 + r0;
    int s0p = seg*WSEG + 4*p0 + (h & 3);
    int s1p = s0p + 32;
    float* ob0 = out + ((long)b*SLEN + s0p)*HID + h*DHEAD + dc;
    float* ob1 = out + ((long)b*SLEN + s1p)*HID + h*DHEAD + dc;
    #pragma unroll
    for (int j = 0; j < 8; ++j) {
        float2 v0 = make_float2(o[j][0]*inv0, o[j][1]*inv0);
        float2 v1 = make_float2(o[j][2]*inv1, o[j][3]*inv1);
        *(float2*)(ob0 + j*8) = v0;
        *(float2*)(ob1 + j*8) = v1;
    }
}

// ---------------------------------------------------------------------------
extern "C" void kernel_launch(void* const* d_in, const int* in_sizes, int n_in,
                              void* d_out, int out_size)
{
    const float* X   = (const float*)d_in[0];
    const float* Wq  = (const float*)d_in[1];
    const float* bq  = (const float*)d_in[2];
    const float* Wkv = (const float*)d_in[3];
    const float* bkv = (const float*)d_in[4];
    float* out = (float*)d_out;

    cudaMemsetAsync(out, 0, (size_t)out_size * sizeof(float), 0);

    splitx<<<BATCH*SLEN*HID/4/256, 256>>>((const float4*)X);

    dim3 gw(HID/32, NCOL/32, 4);
    wpack<<<gw, 256>>>(Wq, Wkv);

    dim3 g1(NCOL/128, 16, BATCH * 4);
    proj_mma<<<g1, 256>>>(bq, bkv);

    const int smem = (2*BUFE + 128*STR) * (int)sizeof(__half);   // 55296 B
    cudaFuncSetAttribute(attn_mma, cudaFuncAttributeMaxDynamicSharedMemorySize, smem);
    dim3 g2(4, NHEAD, BATCH * NSEG);
    attn_mma<<<g2, 256, smem>>>(out);
}

// round 17
// speedup vs baseline: 2.3580x; 1.2130x over previous
#include <cuda_runtime.h>
#include <cuda_fp16.h>
#include <cstdint>

#define BATCH 2
#define SLEN  8192
#define HID   1024
#define NSEG  4
#define NPTS  512
#define NHEAD 16
#define DHEAD 64
#define WSEG  2048
#define NCOL  768
#define STR   72   // attn smem stride (fp16)

#define GSIZE (BATCH*NSEG*NHEAD*NPTS*DHEAD)
__device__ __align__(16) __half g_Xh[BATCH*SLEN*HID];         // X rounded to fp16
__device__ __align__(16) __half g_Wp[4*NCOL*HID];             // [r][n][k]
__device__ __align__(16) __half g_Qh[GSIZE];                  // [b][seg][h][p][d], pre-scaled
__device__ __align__(16) __half g_Kh[GSIZE];                  // [b][seg][h][p][d]
__device__ __align__(16) __half g_Vth[GSIZE];                 // [b][seg][h][d][p]

// ---------------------------------------------------------------------------
__device__ __forceinline__ void ldm_x4(uint32_t* r, uint32_t addr) {
    asm volatile("ldmatrix.sync.aligned.m8n8.x4.shared.b16 {%0,%1,%2,%3}, [%4];\n"
                 : "=r"(r[0]), "=r"(r[1]), "=r"(r[2]), "=r"(r[3]) : "r"(addr));
}
__device__ __forceinline__ void mma16816(float* c, const uint32_t* a,
                                         uint32_t b0, uint32_t b1) {
    asm volatile("mma.sync.aligned.m16n8k16.row.col.f32.f16.f16.f32 "
                 "{%0,%1,%2,%3}, {%4,%5,%6,%7}, {%8,%9}, {%0,%1,%2,%3};\n"
                 : "+f"(c[0]), "+f"(c[1]), "+f"(c[2]), "+f"(c[3])
                 : "r"(a[0]), "r"(a[1]), "r"(a[2]), "r"(a[3]), "r"(b0), "r"(b1));
}
__device__ __forceinline__ void cp16(uint32_t dst, const void* src) {
    asm volatile("cp.async.cg.shared.global [%0], [%1], 16;\n" :: "r"(dst), "l"(src));
}
__device__ __forceinline__ void cp_commit() { asm volatile("cp.async.commit_group;\n"); }
__device__ __forceinline__ void cp_waitall() { asm volatile("cp.async.wait_group 0;\n"); }

__device__ __forceinline__ uint32_t pack_h(float x, float y) {
    __half2 h2; h2.x = __float2half_rn(x); h2.y = __float2half_rn(y);
    return *(uint32_t*)&h2;
}

// ---------------------------------------------------------------------------
__global__ __launch_bounds__(256) void splitx(const float4* __restrict__ X4)
{
    long i = (long)blockIdx.x * 256 + threadIdx.x;
    float4 v = X4[i];
    __half2 h01, h23;
    h01.x = __float2half_rn(v.x); h01.y = __float2half_rn(v.y);
    h23.x = __float2half_rn(v.z); h23.y = __float2half_rn(v.w);
    __half2* H2 = (__half2*)g_Xh;
    H2[2*i] = h01; H2[2*i+1] = h23;
}

// ---------------------------------------------------------------------------
__global__ __launch_bounds__(256) void wpack(const float* __restrict__ Wq,
                                             const float* __restrict__ Wkv)
{
    __shared__ float s[32][33];
    int tx = threadIdx.x & 31, ty = threadIdx.x >> 5;
    int r = blockIdx.z;
    int n = blockIdx.y * 32 + tx;
    int g = n >> 8, cc = n & 255;
    int h = r + 4 * (cc >> 6), d = cc & 63;
    const float* src; long stride;
    if (g == 0)      { src = Wq  + h*64 + d;        stride = 1024; }
    else if (g == 1) { src = Wkv + h*64 + d;        stride = 2048; }
    else             { src = Wkv + 1024 + h*64 + d; stride = 2048; }
    #pragma unroll
    for (int i = 0; i < 4; ++i) {
        int k = blockIdx.x * 32 + ty + i * 8;
        s[ty + i*8][tx] = src[(long)k * stride];
    }
    __syncthreads();
    long rbase = (long)r * NCOL * HID;
    #pragma unroll
    for (int i = 0; i < 4; ++i) {
        int nl = ty + i * 8;
        float v = s[tx][nl];
        long idx = (long)(blockIdx.y * 32 + nl) * HID + blockIdx.x * 32 + tx;
        g_Wp[rbase + idx] = __float2half_rn(v);
    }
}

// ---------------------------------------------------------------------------
// proj: single-term fp16 mma, 3-stage cp.async pipeline, k-blocks of 32.
// Stage: A 128x40h (10240 B) + B 128x40h, padded stride (conflict-free LDSM).
// ---------------------------------------------------------------------------
#define PSTRIDE 40
#define PABUF   (128*PSTRIDE*2)     // 10240 B
#define PSTG    (2*PABUF)           // 20480 B per stage
#define PSMEM   (3*PSTG)            // 61440 B

__global__ __launch_bounds__(256, 2) void proj_mma(const float* __restrict__ bq,
                                                   const float* __restrict__ bkv)
{
    extern __shared__ __half psm[];
    const uint32_t base = (uint32_t)__cvta_generic_to_shared(psm);

    const int tid  = threadIdx.x;
    const int lane = tid & 31, warp = tid >> 5;
    const int wm = warp >> 2, wn = warp & 3;
    const int b  = blockIdx.z >> 2;
    const int r  = blockIdx.z & 3;
    const int m0 = blockIdx.y * 128;
    const int n0 = blockIdx.x * 128;

    // loader: thread t -> row t>>1, 32-half half-row (t&1), 2x16B per array
    const int lrow = tid >> 1;
    const int kh   = (tid & 1) * 16;
    const __half* aG = g_Xh + ((long)b * SLEN + (4*(m0 + lrow) + r)) * HID + kh;
    const __half* bG = g_Wp + ((long)r * NCOL + n0 + lrow) * HID + kh;
    const uint32_t sa  = base + (uint32_t)(lrow * PSTRIDE + kh) * 2;
    const uint32_t sbb = sa + PABUF;

    // prologue: stages 0,1
    #pragma unroll
    for (int s = 0; s < 2; ++s) {
        const uint32_t so = (uint32_t)s * PSTG;
        const int ko = s * 32;
        cp16(sa + so,       aG + ko);
        cp16(sa + so + 16,  aG + ko + 8);
        cp16(sbb + so,      bG + ko);
        cp16(sbb + so + 16, bG + ko + 8);
        cp_commit();
    }

    const int lrow16 = (lane & 7) + ((lane >> 3) & 1) * 8;
    const int kbyt   = (lane >> 4) * 16;
    const uint32_t aBase = (uint32_t)((wm*64 + lrow16) * PSTRIDE) * 2;
    const uint32_t bBase = (uint32_t)((wn*32 + lrow16) * PSTRIDE) * 2;

    float acc[4][4][4];
    #pragma unroll
    for (int i = 0; i < 4; ++i)
        #pragma unroll
        for (int j = 0; j < 4; ++j)
            #pragma unroll
            for (int q = 0; q < 4; ++q) acc[i][j][q] = 0.f;

    int buf = 0, nbuf = 2;
    for (int kb = 0; kb < 32; ++kb) {
        if (kb < 31) asm volatile("cp.async.wait_group 1;" ::: "memory");
        else         asm volatile("cp.async.wait_group 0;" ::: "memory");
        __syncthreads();   // data for stage kb ready AND all warps done with kb-1

        if (kb + 2 < 32) {   // prefetch stage kb+2 into buffer finished at kb-1
            const uint32_t so = (uint32_t)nbuf * PSTG;
            const int ko = (kb + 2) * 32;
            cp16(sa + so,       aG + ko);
            cp16(sa + so + 16,  aG + ko + 8);
            cp16(sbb + so,      bG + ko);
            cp16(sbb + so + 16, bG + ko + 8);
            cp_commit();
        }

        const uint32_t sA = base + (uint32_t)buf * PSTG;
        const uint32_t sB = sA + PABUF;
        #pragma unroll
        for (int kk = 0; kk < 2; ++kk) {
            const uint32_t colb = (uint32_t)(kk*32 + kbyt);
            uint32_t fbh[2][4];
            ldm_x4(fbh[0], sB + bBase + colb);
            ldm_x4(fbh[1], sB + bBase + (uint32_t)(16*PSTRIDE)*2 + colb);
            #pragma unroll
            for (int mi = 0; mi < 4; ++mi) {
                uint32_t fah[4];
                ldm_x4(fah, sA + aBase + (uint32_t)(mi*16*PSTRIDE)*2 + colb);
                #pragma unroll
                for (int nj = 0; nj < 4; ++nj) {
                    int t = nj >> 1, s2 = nj & 1;
                    mma16816(acc[mi][nj], fah, fbh[t][s2], fbh[t][s2+2]);
                }
            }
        }
        buf  = (buf == 2)  ? 0 : buf + 1;
        nbuf = (nbuf == 2) ? 0 : nbuf + 1;
    }

    // epilogue (all outputs single fp16; Q pre-scaled, V transposed)
    const int group = lane >> 2, tig = lane & 3;
    #pragma unroll
    for (int mi = 0; mi < 4; ++mi) {
        #pragma unroll
        for (int nj = 0; nj < 4; ++nj) {
            int nl = wn*32 + nj*8 + tig*2;
            int c  = n0 + nl;
            int g  = c >> 8, cc = c & 255;
            int hh = r + 4 * (cc >> 6), d = cc & 63;
            const float* barr = (g == 0) ? bq : (g == 1) ? bkv : bkv + 1024;
            float b0v = barr[hh*64 + d], b1v = barr[hh*64 + d + 1];
            #pragma unroll
            for (int half = 0; half < 2; ++half) {
                int jrow = m0 + wm*64 + mi*16 + group + half*8;
                int seg = jrow >> 9, p = jrow & 511;
                float vx = acc[mi][nj][half*2 + 0] + b0v;
                float vy = acc[mi][nj][half*2 + 1] + b1v;
                long bsh = (long)((b*NSEG + seg)*NHEAD + hh);
                if (g == 0) {
                    long idx = (bsh*NPTS + p)*DHEAD + d;
                    *(uint32_t*)&g_Qh[idx] = pack_h(vx * 0.125f, vy * 0.125f);
                } else if (g == 1) {
                    long idx = (bsh*NPTS + p)*DHEAD + d;
                    *(uint32_t*)&g_Kh[idx] = pack_h(vx, vy);
                } else {
                    long idx = (bsh*DHEAD + d)*NPTS + p;
                    g_Vth[idx]        = __float2half_rn(vx);
                    g_Vth[idx + NPTS] = __float2half_rn(vy);
                }
            }
        }
    }
}

// ---------------------------------------------------------------------------
// Flash attention fp16, single-plane (unchanged from R15): S = Qh Kh; O = Ph Vh.
// ---------------------------------------------------------------------------
#define BUFE (128*STR)
#define QOFF (2*BUFE)

__global__ __launch_bounds__(256, 2) void attn_mma(float* __restrict__ out)
{
    extern __shared__ __half sbm[];
    const int tid = threadIdx.x;
    const int lane = tid & 31, warp = tid >> 5;
    const int qt = blockIdx.x, h = blockIdx.y, bs = blockIdx.z;
    const int b = bs >> 2, seg = bs & 3;
    const long base = (long)(bs*NHEAD + h) * (NPTS*DHEAD);

    const uint32_t sm0 = (uint32_t)__cvta_generic_to_shared(sbm);

    const int crow = tid >> 1, chalf = tid & 1;
    const int lm = crow >> 6, lj = crow & 63;
    const __half* csrc = (lm == 0)
        ? g_Kh  + base + lj*DHEAD + chalf*32
        : g_Vth + base + (long)lj*NPTS + chalf*32;
    const long cstep = (lm == 0) ? 64*DHEAD : 64;
    const uint32_t cdst = sm0 + (uint32_t)((lm*64 + lj)*STR)*2 + (uint32_t)chalf*64;

    {
        int qrow = tid >> 1, qhalf = tid & 1;
        const __half* qs = g_Qh + base + (long)(qt*128 + qrow)*DHEAD + qhalf*32;
        uint32_t qd = sm0 + (uint32_t)(QOFF + qrow*STR)*2 + (uint32_t)qhalf*64;
        #pragma unroll
        for (int i = 0; i < 4; ++i) cp16(qd + i*16, qs + i*8);
        #pragma unroll
        for (int i = 0; i < 4; ++i) cp16(cdst + i*16, csrc + i*8);
    }
    cp_commit();
    cp_waitall();
    __syncthreads();

    const int lrow16 = (lane & 7) + ((lane >> 3) & 1) * 8;
    const int kbyt   = (lane >> 4) * 16;

    uint32_t qh[4][4];
    {
        uint32_t qa = sm0 + (uint32_t)(QOFF + (warp*16 + lrow16)*STR)*2 + kbyt;
        #pragma unroll
        for (int kk = 0; kk < 4; ++kk) ldm_x4(qh[kk], qa + kk*32);
    }
    {
        const __half* s = csrc + cstep;
        uint32_t d = cdst + (uint32_t)BUFE*2;
        #pragma unroll
        for (int i = 0; i < 4; ++i) cp16(d + i*16, s + i*8);
    }
    cp_commit();

    float m0 = -1e30f, m1 = -1e30f, l0 = 0.f, l1 = 0.f;
    float o[8][4];
    #pragma unroll
    for (int j = 0; j < 8; ++j)
        #pragma unroll
        for (int q = 0; q < 4; ++q) o[j][q] = 0.f;

    for (int ck = 0; ck < 8; ++ck) {
        const uint32_t sK = sm0 + (uint32_t)(ck & 1)*BUFE*2;
        const uint32_t sV = sK + 64*STR*2;

        float sc[8][4];
        #pragma unroll
        for (int j = 0; j < 8; ++j)
            #pragma unroll
            for (int q = 0; q < 4; ++q) sc[j][q] = 0.f;

        #pragma unroll
        for (int kk = 0; kk < 4; ++kk) {
            uint32_t kbh[4][4];
            #pragma unroll
            for (int kg = 0; kg < 4; ++kg) {
                uint32_t a = (uint32_t)((kg*16 + lrow16)*STR*2 + kk*32 + kbyt);
                ldm_x4(kbh[kg], sK + a);
            }
            #pragma unroll
            for (int kg = 0; kg < 4; ++kg)
                #pragma unroll
                for (int s = 0; s < 2; ++s)
                    mma16816(sc[kg*2 + s], qh[kk], kbh[kg][s], kbh[kg][s+2]);
        }

        float mc0 = -1e30f, mc1 = -1e30f;
        #pragma unroll
        for (int j = 0; j < 8; ++j) {
            mc0 = fmaxf(mc0, fmaxf(sc[j][0], sc[j][1]));
            mc1 = fmaxf(mc1, fmaxf(sc[j][2], sc[j][3]));
        }
        mc0 = fmaxf(mc0, __shfl_xor_sync(0xffffffffu, mc0, 1));
        mc0 = fmaxf(mc0, __shfl_xor_sync(0xffffffffu, mc0, 2));
        mc1 = fmaxf(mc1, __shfl_xor_sync(0xffffffffu, mc1, 1));
        mc1 = fmaxf(mc1, __shfl_xor_sync(0xffffffffu, mc1, 2));
        float mn0 = fmaxf(m0, mc0), mn1 = fmaxf(m1, mc1);
        float a0 = __expf(m0 - mn0), a1 = __expf(m1 - mn1);
        float s0 = 0.f, s1 = 0.f;
        #pragma unroll
        for (int j = 0; j < 8; ++j) {
            sc[j][0] = __expf(sc[j][0] - mn0);
            sc[j][1] = __expf(sc[j][1] - mn0);
            sc[j][2] = __expf(sc[j][2] - mn1);
            sc[j][3] = __expf(sc[j][3] - mn1);
            s0 += sc[j][0] + sc[j][1];
            s1 += sc[j][2] + sc[j][3];
        }
        s0 += __shfl_xor_sync(0xffffffffu, s0, 1);
        s0 += __shfl_xor_sync(0xffffffffu, s0, 2);
        s1 += __shfl_xor_sync(0xffffffffu, s1, 1);
        s1 += __shfl_xor_sync(0xffffffffu, s1, 2);
        l0 = l0*a0 + s0; l1 = l1*a1 + s1;
        m0 = mn0; m1 = mn1;
        #pragma unroll
        for (int j = 0; j < 8; ++j) {
            o[j][0] *= a0; o[j][1] *= a0;
            o[j][2] *= a1; o[j][3] *= a1;
        }

        uint32_t ph[4][4];
        #pragma unroll
        for (int t = 0; t < 4; ++t) {
            ph[t][0] = pack_h(sc[2*t  ][0], sc[2*t  ][1]);
            ph[t][1] = pack_h(sc[2*t  ][2], sc[2*t  ][3]);
            ph[t][2] = pack_h(sc[2*t+1][0], sc[2*t+1][1]);
            ph[t][3] = pack_h(sc[2*t+1][2], sc[2*t+1][3]);
        }

        #pragma unroll
        for (int t = 0; t < 4; ++t) {
            uint32_t vbh[4][4];
            #pragma unroll
            for (int nt = 0; nt < 4; ++nt) {
                uint32_t a = (uint32_t)((nt*16 + lrow16)*STR*2 + t*32 + kbyt);
                ldm_x4(vbh[nt], sV + a);
            }
            #pragma unroll
            for (int nt = 0; nt < 4; ++nt)
                #pragma unroll
                for (int s = 0; s < 2; ++s)
                    mma16816(o[nt*2 + s], ph[t], vbh[nt][s], vbh[nt][s+2]);
        }

        cp_waitall();
        __syncthreads();
        if (ck + 2 < 8) {
            const __half* s = csrc + (long)(ck + 2)*cstep;
            uint32_t d = cdst + (uint32_t)(ck & 1)*BUFE*2;
            #pragma unroll
            for (int i = 0; i < 4; ++i) cp16(d + i*16, s + i*8);
            cp_commit();
        }
    }

    // epilogue
    float inv0 = 1.f / l0, inv1 = 1.f / l1;
    int r0 = lane >> 2, dc = (lane & 3) * 2;
    int p0 = qt*128 + warp*16 + r0;
    int s0p = seg*WSEG + 4*p0 + (h & 3);
    int s1p = s0p + 32;
    float* ob0 = out + ((long)b*SLEN + s0p)*HID + h*DHEAD + dc;
    float* ob1 = out + ((long)b*SLEN + s1p)*HID + h*DHEAD + dc;
    #pragma unroll
    for (int j = 0; j < 8; ++j) {
        float2 v0 = make_float2(o[j][0]*inv0, o[j][1]*inv0);
        float2 v1 = make_float2(o[j][2]*inv1, o[j][3]*inv1);
        *(float2*)(ob0 + j*8) = v0;
        *(float2*)(ob1 + j*8) = v1;
    }
}

// ---------------------------------------------------------------------------
extern "C" void kernel_launch(void* const* d_in, const int* in_sizes, int n_in,
                              void* d_out, int out_size)
{
    const float* X   = (const float*)d_in[0];
    const float* Wq  = (const float*)d_in[1];
    const float* bq  = (const float*)d_in[2];
    const float* Wkv = (const float*)d_in[3];
    const float* bkv = (const float*)d_in[4];
    float* out = (float*)d_out;

    cudaMemsetAsync(out, 0, (size_t)out_size * sizeof(float), 0);

    splitx<<<BATCH*SLEN*HID/4/256, 256>>>((const float4*)X);

    dim3 gw(HID/32, NCOL/32, 4);
    wpack<<<gw, 256>>>(Wq, Wkv);

    cudaFuncSetAttribute(proj_mma, cudaFuncAttributeMaxDynamicSharedMemorySize, PSMEM);
    dim3 g1(NCOL/128, 16, BATCH * 4);
    proj_mma<<<g1, 256, PSMEM>>>(bq, bkv);

    const int smem = (2*BUFE + 128*STR) * (int)sizeof(__half);   // 55296 B
    cudaFuncSetAttribute(attn_mma, cudaFuncAttributeMaxDynamicSharedMemorySize, smem);
    dim3 g2(4, NHEAD, BATCH * NSEG);
    attn_mma<<<g2, 256, smem>>>(out);
}